// round 2
// baseline (speedup 1.0000x reference)
#include <cuda_runtime.h>
#include <cuda_bf16.h>
#include <math.h>

// Problem constants
#define BB 2
#define NQ 900
#define CC 256
#define HH 8
#define NN 4096
#define DH 32
#define HID 512

// -------- scratch (device globals; no allocation allowed) --------
__device__ float g_q [BB*NQ*CC];     // scaled Q projection
__device__ float g_k [BB*NN*CC];
__device__ float g_v [BB*NN*CC];
__device__ float g_kt[BB*HH*DH*NN];  // [bh][d][n]
__device__ float g_vt[BB*HH*DH*NN];
__device__ float g_rx[BB*NQ*64*HH];
__device__ float g_ry[BB*NQ*64*HH];
__device__ float g_ao[BB*NQ*CC];     // attention out pre-projection

// =====================================================================
// Generic GEMM: out[M,256] = A[M,256] @ W[256,256]; out = (acc+bias)*scale
// BM=64, BN=64, BK=16; 256 threads; 4x4 per thread.
// =====================================================================
__global__ __launch_bounds__(256) void gemm256_kernel(
    const float* __restrict__ A, const float* __restrict__ W,
    const float* __restrict__ bias, float* __restrict__ out,
    int M, float scale)
{
    __shared__ float As[16][64];
    __shared__ float Ws[16][64];
    const int tid = threadIdx.x;
    const int tx = tid & 15, ty = tid >> 4;
    const int bm = blockIdx.y * 64, bn = blockIdx.x * 64;

    float acc[4][4] = {};

    for (int kt = 0; kt < 256; kt += 16) {
        // A tile: 64 rows x 16 cols -> As[k][m]
        {
            int r = tid >> 2, c4 = (tid & 3) * 4;
            int row = bm + r;
            float4 v = (row < M) ? *(const float4*)&A[row*256 + kt + c4]
                                 : make_float4(0.f,0.f,0.f,0.f);
            As[c4+0][r] = v.x; As[c4+1][r] = v.y; As[c4+2][r] = v.z; As[c4+3][r] = v.w;
        }
        // W tile: 16 rows x 64 cols
        {
            int r = tid >> 4, c4 = (tid & 15) * 4;
            *(float4*)&Ws[r][c4] = *(const float4*)&W[(kt + r)*256 + bn + c4];
        }
        __syncthreads();
        #pragma unroll
        for (int k = 0; k < 16; k++) {
            float4 a4 = *(const float4*)&As[k][ty*4];
            float4 b4 = *(const float4*)&Ws[k][tx*4];
            float a[4] = {a4.x, a4.y, a4.z, a4.w};
            float b[4] = {b4.x, b4.y, b4.z, b4.w};
            #pragma unroll
            for (int i = 0; i < 4; i++)
                #pragma unroll
                for (int j = 0; j < 4; j++)
                    acc[i][j] += a[i] * b[j];
        }
        __syncthreads();
    }
    float4 bv = *(const float4*)&bias[bn + tx*4];
    float bb[4] = {bv.x, bv.y, bv.z, bv.w};
    #pragma unroll
    for (int i = 0; i < 4; i++) {
        int row = bm + ty*4 + i;
        if (row < M) {
            float4 o;
            o.x = (acc[i][0] + bb[0]) * scale;
            o.y = (acc[i][1] + bb[1]) * scale;
            o.z = (acc[i][2] + bb[2]) * scale;
            o.w = (acc[i][3] + bb[3]) * scale;
            *(float4*)&out[row*256 + bn + tx*4] = o;
        }
    }
}

// =====================================================================
// Transpose K/V projections: in[(b*N+n)*C + h*32 + d] -> out[bh*32*N + d*N + n]
// =====================================================================
__global__ __launch_bounds__(256) void transpose_kernel(
    const float* __restrict__ in, float* __restrict__ out)
{
    __shared__ float t[32][33];
    const int bh = blockIdx.y;
    const int b = bh >> 3, h = bh & 7;
    const int n0 = blockIdx.x * 32;
    const int tx = threadIdx.x, ty = threadIdx.y; // 32 x 8
    #pragma unroll
    for (int i = 0; i < 4; i++) {
        int n = n0 + ty + i*8;
        t[ty + i*8][tx] = in[(b*NN + n)*CC + h*32 + tx];
    }
    __syncthreads();
    #pragma unroll
    for (int i = 0; i < 4; i++) {
        int d = ty + i*8;
        out[((size_t)bh*32 + d)*NN + n0 + tx] = t[tx][d];
    }
}

// =====================================================================
// RPE MLP: one CTA per (b,q). rows 0..63 -> x-axis pos, 64..127 -> y-axis.
// hidden_j = relu(d0*W1[0,j] + d1*W1[1,j] + b1[j]);  out[h] = sum_j hidden_j*W2[j,h]
// =====================================================================
__global__ __launch_bounds__(256) void rpe_kernel(
    const float* __restrict__ ref,
    const float* __restrict__ W1x, const float* __restrict__ b1x, const float* __restrict__ W2x,
    const float* __restrict__ W1y, const float* __restrict__ b1y, const float* __restrict__ W2y,
    float* __restrict__ rx, float* __restrict__ ry)
{
    __shared__ float sW1[2][1024];
    __shared__ float sb1[2][512];
    __shared__ float sW2[2][4096];
    const int bq = blockIdx.x;
    const int tid = threadIdx.x;

    for (int i = tid; i < 1024; i += 256) { sW1[0][i] = W1x[i]; sW1[1][i] = W1y[i]; }
    for (int i = tid; i < 512;  i += 256) { sb1[0][i] = b1x[i]; sb1[1][i] = b1y[i]; }
    for (int i = tid; i < 4096; i += 256) { sW2[0][i] = W2x[i]; sW2[1][i] = W2y[i]; }
    float4 box = *(const float4*)&ref[bq*4];   // cx, cy, w, h
    __syncthreads();

    const int w = tid >> 5, lane = tid & 31;
    const int axis = w >> 2;
    const float lo = (axis == 0) ? box.x - box.z*0.5f : box.y - box.w*0.5f;
    const float hi = (axis == 0) ? box.x + box.z*0.5f : box.y + box.w*0.5f;
    const float* w1 = sW1[axis];
    const float* b1 = sb1[axis];
    const float* w2 = sW2[axis];
    float* outp = (axis == 0) ? rx : ry;
    const int pos0 = (w & 3) * 16;

    for (int g = 0; g < 2; g++) {
        float d0[8], d1[8];
        #pragma unroll
        for (int r = 0; r < 8; r++) {
            float p = ((float)(pos0 + g*8 + r) + 0.5f) * 16.0f;
            d0[r] = lo - p;
            d1[r] = hi - p;
        }
        float acc[8][8];
        #pragma unroll
        for (int r = 0; r < 8; r++)
            #pragma unroll
            for (int h = 0; h < 8; h++) acc[r][h] = 0.f;

        for (int jj = 0; jj < 16; jj++) {
            int j = jj*32 + lane;
            float u = w1[j], v = w1[512 + j], bb = b1[j];
            float w2v[8];
            #pragma unroll
            for (int h = 0; h < 8; h++) w2v[h] = w2[j*8 + h];
            #pragma unroll
            for (int r = 0; r < 8; r++) {
                float hv = fmaxf(d0[r]*u + d1[r]*v + bb, 0.f);
                #pragma unroll
                for (int h = 0; h < 8; h++) acc[r][h] += hv * w2v[h];
            }
        }
        #pragma unroll
        for (int r = 0; r < 8; r++) {
            #pragma unroll
            for (int h = 0; h < 8; h++) {
                float v = acc[r][h];
                #pragma unroll
                for (int o = 16; o; o >>= 1) v += __shfl_xor_sync(0xffffffffu, v, o);
                if (lane == h)
                    outp[(bq*64 + pos0 + g*8 + r)*8 + h] = v;
            }
        }
    }
}

// =====================================================================
// Fused attention (flash-style online softmax).
// Grid: (ceil(NQ/8), B*H). Block: 128 threads = 4 warps, 2 queries/warp.
// Each lane owns 4 consecutive keys per 128-key tile (float4 K/V loads).
// =====================================================================
__global__ __launch_bounds__(128) void attn_kernel(
    const float* __restrict__ qp, const float* __restrict__ kt,
    const float* __restrict__ vt, const float* __restrict__ rx,
    const float* __restrict__ ry, const unsigned char* __restrict__ mask,
    float* __restrict__ ao)
{
    __shared__ float Ks[32][128];
    __shared__ float Vs[32][128];
    __shared__ float rxs[8][64], rys[8][64];
    __shared__ float madd[128];

    const int tid = threadIdx.x;
    const int w = tid >> 5, lane = tid & 31;
    const int bh = blockIdx.y, b = bh >> 3, h = bh & 7;
    const int base_q = blockIdx.x * 8;
    const int qA = base_q + w, qB = base_q + w + 4;
    const bool vA = (qA < NQ), vB = (qB < NQ);
    const int qAc = vA ? qA : (NQ - 1);
    const int qBc = vB ? qB : (NQ - 1);

    float qra[32], qrb[32];
    {
        const float* pa = qp + (b*NQ + qAc)*CC + h*32;
        const float* pb = qp + (b*NQ + qBc)*CC + h*32;
        #pragma unroll
        for (int d = 0; d < 32; d++) { qra[d] = pa[d]; qrb[d] = pb[d]; }
    }
    for (int i = lane; i < 64; i += 32) {
        rxs[w][i]     = rx[((b*NQ + qAc)*64 + i)*8 + h];
        rys[w][i]     = ry[((b*NQ + qAc)*64 + i)*8 + h];
        rxs[w + 4][i] = rx[((b*NQ + qBc)*64 + i)*8 + h];
        rys[w + 4][i] = ry[((b*NQ + qBc)*64 + i)*8 + h];
    }

    const float* ktp = kt + (size_t)bh*32*NN;
    const float* vtp = vt + (size_t)bh*32*NN;

    float mA = -3.4e38f, lA = 0.f, mB = -3.4e38f, lB = 0.f;
    float accA[32], accB[32];
    #pragma unroll
    for (int d = 0; d < 32; d++) { accA[d] = 0.f; accB[d] = 0.f; }

    for (int t = 0; t < 32; t++) {
        __syncthreads();
        const int base = t * 128;
        #pragma unroll
        for (int r = 0; r < 8; r++) {
            int lin = tid + r*128;             // 0..1023
            int d = lin >> 5, i4 = (lin & 31) * 4;
            *(float4*)&Ks[d][i4] = *(const float4*)&ktp[d*NN + base + i4];
            *(float4*)&Vs[d][i4] = *(const float4*)&vtp[d*NN + base + i4];
        }
        if (tid < 128) madd[tid] = mask[b*NN + base + tid] ? -100.f : 0.f;
        __syncthreads();

        float sA[4], sB[4];
        #pragma unroll
        for (int c = 0; c < 4; c++) {
            int kl = lane*4 + c, kk = base + kl;
            float ma = madd[kl];
            sA[c] = ma + rxs[w][kk & 63]     + rys[w][kk >> 6];
            sB[c] = ma + rxs[w + 4][kk & 63] + rys[w + 4][kk >> 6];
        }
        #pragma unroll
        for (int d = 0; d < 32; d++) {
            float4 kv = *(const float4*)&Ks[d][lane*4];
            float a = qra[d], bq2 = qrb[d];
            sA[0] += a*kv.x; sA[1] += a*kv.y; sA[2] += a*kv.z; sA[3] += a*kv.w;
            sB[0] += bq2*kv.x; sB[1] += bq2*kv.y; sB[2] += bq2*kv.z; sB[3] += bq2*kv.w;
        }
        // online softmax update (per-tile rescale)
        float mxA = fmaxf(fmaxf(sA[0], sA[1]), fmaxf(sA[2], sA[3]));
        float mxB = fmaxf(fmaxf(sB[0], sB[1]), fmaxf(sB[2], sB[3]));
        float mnA = fmaxf(mA, mxA), mnB = fmaxf(mB, mxB);
        float cA = __expf(mA - mnA), cB = __expf(mB - mnB);
        mA = mnA; mB = mnB;
        float pA[4], pB[4];
        lA *= cA; lB *= cB;
        #pragma unroll
        for (int c = 0; c < 4; c++) {
            pA[c] = __expf(sA[c] - mnA); lA += pA[c];
            pB[c] = __expf(sB[c] - mnB); lB += pB[c];
        }
        #pragma unroll
        for (int d = 0; d < 32; d++) {
            float4 vv = *(const float4*)&Vs[d][lane*4];
            accA[d] = accA[d]*cA + pA[0]*vv.x + pA[1]*vv.y + pA[2]*vv.z + pA[3]*vv.w;
            accB[d] = accB[d]*cB + pB[0]*vv.x + pB[1]*vv.y + pB[2]*vv.z + pB[3]*vv.w;
        }
    }

    // cross-lane merge, query A
    {
        float ml = mA;
        #pragma unroll
        for (int o = 16; o; o >>= 1) mA = fmaxf(mA, __shfl_xor_sync(0xffffffffu, mA, o));
        float corr = __expf(ml - mA);
        lA *= corr;
        #pragma unroll
        for (int o = 16; o; o >>= 1) lA += __shfl_xor_sync(0xffffffffu, lA, o);
        float keep = 0.f;
        #pragma unroll
        for (int d = 0; d < 32; d++) {
            float v = accA[d] * corr;
            #pragma unroll
            for (int o = 16; o; o >>= 1) v += __shfl_xor_sync(0xffffffffu, v, o);
            if (lane == d) keep = v;
        }
        if (vA) ao[(b*NQ + qA)*CC + h*32 + lane] = keep / lA;
    }
    // cross-lane merge, query B
    {
        float ml = mB;
        #pragma unroll
        for (int o = 16; o; o >>= 1) mB = fmaxf(mB, __shfl_xor_sync(0xffffffffu, mB, o));
        float corr = __expf(ml - mB);
        lB *= corr;
        #pragma unroll
        for (int o = 16; o; o >>= 1) lB += __shfl_xor_sync(0xffffffffu, lB, o);
        float keep = 0.f;
        #pragma unroll
        for (int d = 0; d < 32; d++) {
            float v = accB[d] * corr;
            #pragma unroll
            for (int o = 16; o; o >>= 1) v += __shfl_xor_sync(0xffffffffu, v, o);
            if (lane == d) keep = v;
        }
        if (vB) ao[(b*NQ + qB)*CC + h*32 + lane] = keep / lB;
    }
}

// =====================================================================
// Launch
// =====================================================================
extern "C" void kernel_launch(void* const* d_in, const int* in_sizes, int n_in,
                              void* d_out, int out_size)
{
    const float* query = (const float*)d_in[1];
    const float* ref   = (const float*)d_in[2];
    const float* kin   = (const float*)d_in[3];
    const float* vin   = (const float*)d_in[4];
    const unsigned char* mask = (const unsigned char*)d_in[6];
    const float* W1x = (const float*)d_in[7];
    const float* b1x = (const float*)d_in[8];
    const float* W2x = (const float*)d_in[9];
    const float* W1y = (const float*)d_in[10];
    const float* b1y = (const float*)d_in[11];
    const float* W2y = (const float*)d_in[12];
    const float* Wq  = (const float*)d_in[13];
    const float* bq  = (const float*)d_in[14];
    const float* Wk  = (const float*)d_in[15];
    const float* bk  = (const float*)d_in[16];
    const float* Wv  = (const float*)d_in[17];
    const float* bv  = (const float*)d_in[18];
    const float* Wp  = (const float*)d_in[19];
    const float* bp  = (const float*)d_in[20];
    float* out = (float*)d_out;

    void *pq, *pk, *pv, *pkt, *pvt, *prx, *pry, *pao;
    cudaGetSymbolAddress(&pq,  g_q);
    cudaGetSymbolAddress(&pk,  g_k);
    cudaGetSymbolAddress(&pv,  g_v);
    cudaGetSymbolAddress(&pkt, g_kt);
    cudaGetSymbolAddress(&pvt, g_vt);
    cudaGetSymbolAddress(&prx, g_rx);
    cudaGetSymbolAddress(&pry, g_ry);
    cudaGetSymbolAddress(&pao, g_ao);

    const float scale = 0.17677669529663687f; // 32^-0.5
    const int MQ = BB * NQ;   // 1800
    const int MK = BB * NN;   // 8192

    gemm256_kernel<<<dim3(4, (MQ + 63)/64), 256>>>(query, Wq, bq, (float*)pq, MQ, scale);
    gemm256_kernel<<<dim3(4, MK/64), 256>>>(kin, Wk, bk, (float*)pk, MK, 1.0f);
    gemm256_kernel<<<dim3(4, MK/64), 256>>>(vin, Wv, bv, (float*)pv, MK, 1.0f);

    transpose_kernel<<<dim3(NN/32, BB*HH), dim3(32,8)>>>((const float*)pk, (float*)pkt);
    transpose_kernel<<<dim3(NN/32, BB*HH), dim3(32,8)>>>((const float*)pv, (float*)pvt);

    rpe_kernel<<<MQ, 256>>>(ref, W1x, b1x, W2x, W1y, b1y, W2y, (float*)prx, (float*)pry);

    attn_kernel<<<dim3((NQ + 7)/8, BB*HH), 128>>>(
        (const float*)pq, (const float*)pkt, (const float*)pvt,
        (const float*)prx, (const float*)pry, mask, (float*)pao);

    gemm256_kernel<<<dim3(4, (MQ + 63)/64), 256>>>((const float*)pao, Wp, bp, out, MQ, 1.0f);
}

// round 4
// speedup vs baseline: 1.8463x; 1.8463x over previous
#include <cuda_runtime.h>
#include <cuda_fp16.h>
#include <cstdint>

#define BB 2
#define NQ 900
#define CC 256
#define HH 8
#define NN 4096
#define DH 32

__device__ float g_q [BB*NQ*CC];
__device__ float g_k [BB*NN*CC];
__device__ float g_v [BB*NN*CC];
__device__ uint2 g_kf[BB*HH*512*2*32];   // S-mma B fragments
__device__ uint2 g_vf[BB*HH*256*4*32];   // PV-mma B fragments
__device__ unsigned g_mb[BB*128];        // mask bitset
__device__ float g_rx[BB*HH*NQ*64];
__device__ float g_ry[BB*HH*NQ*64];
__device__ float g_ao[BB*NQ*CC];

__device__ __forceinline__ uint32_t pack_h2(float lo, float hi){
    uint32_t r; asm("cvt.rn.f16x2.f32 %0, %1, %2;" : "=r"(r) : "f"(hi), "f"(lo)); return r;
}
__device__ __forceinline__ float ex2f(float x){ float r; asm("ex2.approx.f32 %0, %1;":"=f"(r):"f"(x)); return r; }
__device__ __forceinline__ void mma16816(float* c, const uint32_t* a, uint2 b){
    asm volatile("mma.sync.aligned.m16n8k16.row.col.f32.f16.f16.f32 "
      "{%0,%1,%2,%3}, {%4,%5,%6,%7}, {%8,%9}, {%0,%1,%2,%3};"
      : "+f"(c[0]),"+f"(c[1]),"+f"(c[2]),"+f"(c[3])
      : "r"(a[0]),"r"(a[1]),"r"(a[2]),"r"(a[3]),"r"(b.x),"r"(b.y));
}

// ---------------- GEMM (fp32, K=256) ----------------
__global__ __launch_bounds__(256) void gemm256_kernel(
    const float* __restrict__ A, const float* __restrict__ W,
    const float* __restrict__ bias, float* __restrict__ out, int M, float scale)
{
    __shared__ float As[16][64];
    __shared__ float Ws[16][64];
    const int tid=threadIdx.x, tx=tid&15, ty=tid>>4;
    const int bm=blockIdx.y*64, bn=blockIdx.x*64;
    float acc[4][4]={};
    for (int kt=0;kt<256;kt+=16){
        { int r=tid>>2,c4=(tid&3)*4,row=bm+r;
          float4 v=(row<M)?*(const float4*)&A[row*256+kt+c4]:make_float4(0.f,0.f,0.f,0.f);
          As[c4+0][r]=v.x;As[c4+1][r]=v.y;As[c4+2][r]=v.z;As[c4+3][r]=v.w; }
        { int r=tid>>4,c4=(tid&15)*4;
          *(float4*)&Ws[r][c4]=*(const float4*)&W[(kt+r)*256+bn+c4]; }
        __syncthreads();
        #pragma unroll
        for (int k=0;k<16;k++){
            float4 a4=*(const float4*)&As[k][ty*4];
            float4 b4=*(const float4*)&Ws[k][tx*4];
            float a[4]={a4.x,a4.y,a4.z,a4.w}, b[4]={b4.x,b4.y,b4.z,b4.w};
            #pragma unroll
            for (int i=0;i<4;i++)
                #pragma unroll
                for (int j=0;j<4;j++) acc[i][j]+=a[i]*b[j];
        }
        __syncthreads();
    }
    float4 bv=*(const float4*)&bias[bn+tx*4];
    float bb[4]={bv.x,bv.y,bv.z,bv.w};
    #pragma unroll
    for (int i=0;i<4;i++){
        int row=bm+ty*4+i;
        if (row<M){
            float4 o;
            o.x=(acc[i][0]+bb[0])*scale; o.y=(acc[i][1]+bb[1])*scale;
            o.z=(acc[i][2]+bb[2])*scale; o.w=(acc[i][3]+bb[3])*scale;
            *(float4*)&out[row*256+bn+tx*4]=o;
        }
    }
}

// ---------------- fragment pack kernels ----------------
// Kf: B operand of S=Q*K^T (col-major k=d16 x n=key8).
// idx = bh*32768 + kt8*64 + ds*32 + lane
__global__ __launch_bounds__(256) void pack_kf_kernel(
    const float* __restrict__ k, uint2* __restrict__ Kf)
{
    int idx=blockIdx.x*256+threadIdx.x;
    int lane=idx&31, ds=(idx>>5)&1, kt8=(idx>>6)&511, bh=idx>>15;
    int b=bh>>3, h=bh&7;
    int key=kt8*8+(lane>>2), d0=ds*16+(lane&3)*2;
    const float* src=k+((size_t)b*NN+key)*CC+h*32+d0;
    Kf[idx]=make_uint2(pack_h2(src[0],src[1]), pack_h2(src[8],src[9]));
}
// Vf: B operand of O=P*V (col-major k=key16 x n=d8).
// idx = bh*32768 + kt16*128 + nt*32 + lane
__global__ __launch_bounds__(256) void pack_vf_kernel(
    const float* __restrict__ v, uint2* __restrict__ Vf)
{
    int idx=blockIdx.x*256+threadIdx.x;
    int lane=idx&31, nt=(idx>>5)&3, kt16=(idx>>7)&255, bh=idx>>15;
    int b=bh>>3, h=bh&7;
    int key0=kt16*16+(lane&3)*2, d=nt*8+(lane>>2);
    const float* src=v+((size_t)b*NN+key0)*CC+h*32+d;
    Vf[idx]=make_uint2(pack_h2(src[0],src[CC]), pack_h2(src[8*CC],src[9*CC]));
}
__global__ void pack_mask_kernel(const unsigned char* __restrict__ m, unsigned* __restrict__ mb)
{
    int idx=blockIdx.x*256+threadIdx.x;
    if (idx < BB*128){
        const unsigned char* p=m+idx*32;
        unsigned v=0;
        #pragma unroll
        for (int i=0;i<32;i++) v |= (p[i]?1u:0u)<<i;
        mb[idx]=v;
    }
}

// ---------------- RPE MLP ----------------
__global__ __launch_bounds__(256) void rpe_kernel(
    const float* __restrict__ ref,
    const float* __restrict__ W1x, const float* __restrict__ b1x, const float* __restrict__ W2x,
    const float* __restrict__ W1y, const float* __restrict__ b1y, const float* __restrict__ W2y,
    float* __restrict__ rx, float* __restrict__ ry)
{
    __shared__ float sW1[2][1024];
    __shared__ float sb1[2][512];
    __shared__ float sW2[2][4096];
    const int bq=blockIdx.x, bidx=bq/NQ, qidx=bq%NQ, tid=threadIdx.x;
    for (int i=tid;i<1024;i+=256){ sW1[0][i]=W1x[i]; sW1[1][i]=W1y[i]; }
    for (int i=tid;i<512; i+=256){ sb1[0][i]=b1x[i]; sb1[1][i]=b1y[i]; }
    for (int i=tid;i<4096;i+=256){ sW2[0][i]=W2x[i]; sW2[1][i]=W2y[i]; }
    float4 box=*(const float4*)&ref[bq*4];
    __syncthreads();
    const int w=tid>>5, lane=tid&31, axis=w>>2;
    const float lo=(axis==0)?box.x-box.z*0.5f:box.y-box.w*0.5f;
    const float hi=(axis==0)?box.x+box.z*0.5f:box.y+box.w*0.5f;
    const float *w1=sW1[axis], *b1=sb1[axis], *w2=sW2[axis];
    float* outp=(axis==0)?rx:ry;
    const int pos0=(w&3)*16;
    for (int g=0;g<2;g++){
        float d0[8],d1[8];
        #pragma unroll
        for (int r=0;r<8;r++){ float p=((float)(pos0+g*8+r)+0.5f)*16.0f; d0[r]=lo-p; d1[r]=hi-p; }
        float acc[8][8];
        #pragma unroll
        for (int r=0;r<8;r++)
            #pragma unroll
            for (int h2=0;h2<8;h2++) acc[r][h2]=0.f;
        for (int jj=0;jj<16;jj++){
            int j=jj*32+lane;
            float u=w1[j], v=w1[512+j], bb=b1[j];
            float w2v[8];
            #pragma unroll
            for (int h2=0;h2<8;h2++) w2v[h2]=w2[j*8+h2];
            #pragma unroll
            for (int r=0;r<8;r++){
                float hv=fmaxf(d0[r]*u+d1[r]*v+bb,0.f);
                #pragma unroll
                for (int h2=0;h2<8;h2++) acc[r][h2]+=hv*w2v[h2];
            }
        }
        #pragma unroll
        for (int r=0;r<8;r++)
            #pragma unroll
            for (int h2=0;h2<8;h2++){
                float v=acc[r][h2];
                #pragma unroll
                for (int o=16;o;o>>=1) v+=__shfl_xor_sync(0xffffffffu,v,o);
                if (lane==h2) outp[((size_t)(bidx*8+h2)*NQ+qidx)*64+pos0+g*8+r]=v;
            }
    }
}

// ---------------- HMMA flash attention ----------------
// grid (8 q-tiles, 16 bh), 256 threads (8 warps x 16 query rows).
__global__ __launch_bounds__(256) void attn_hmma_kernel(
    const float* __restrict__ qp, const uint2* __restrict__ Kf, const uint2* __restrict__ Vf,
    const float* __restrict__ rxg, const float* __restrict__ ryg,
    const unsigned* __restrict__ mbits, float* __restrict__ ao)
{
    const int tid=threadIdx.x, wid=tid>>5, lane=tid&31;
    const int g=lane>>2, tg=lane&3;
    const int bh=blockIdx.y, b=bh>>3, h=bh&7;
    const int q0=blockIdx.x*128 + wid*16;
    const float L2E=1.4426950408889634f;
    int qr[2]={q0+g, q0+g+8};
    int qc[2]={qr[0]<NQ?qr[0]:NQ-1, qr[1]<NQ?qr[1]:NQ-1};

    // Q a-fragments (fp16): qf[ds][{a0,a1,a2,a3}]
    uint32_t qf[2][4];
    #pragma unroll
    for (int ds=0;ds<2;ds++)
        #pragma unroll
        for (int r=0;r<2;r++){
            const float* p=qp+((size_t)b*NQ+qc[r])*CC+h*32+ds*16+tg*2;
            qf[ds][r]  =pack_h2(p[0],p[1]);
            qf[ds][r+2]=pack_h2(p[8],p[9]);
        }

    // rx registers + per-row static shift
    float rxv[2][16], shift[2];
    #pragma unroll
    for (int r=0;r<2;r++){
        const float* rp=rxg+((size_t)bh*NQ+qc[r])*64;
        float mx=-1e30f;
        #pragma unroll
        for (int j=0;j<8;j++){
            float2 v=*(const float2*)&rp[j*8+tg*2];
            rxv[r][j*2]=v.x; rxv[r][j*2+1]=v.y;
            mx=fmaxf(mx,fmaxf(v.x,v.y));
        }
        mx=fmaxf(mx,__shfl_xor_sync(0xffffffffu,mx,1));
        mx=fmaxf(mx,__shfl_xor_sync(0xffffffffu,mx,2));
        const float* yp=ryg+((size_t)bh*NQ+qc[r])*64;
        float my=-1e30f;
        #pragma unroll
        for (int j=0;j<16;j++) my=fmaxf(my,yp[tg+4*j]);
        my=fmaxf(my,__shfl_xor_sync(0xffffffffu,my,1));
        my=fmaxf(my,__shfl_xor_sync(0xffffffffu,my,2));
        shift[r]=mx+my;
    }

    const uint2* KfB=Kf+(size_t)bh*32768;
    const uint2* VfB=Vf+(size_t)bh*32768;
    float Oacc[4][4];
    #pragma unroll
    for (int i=0;i<4;i++)
        #pragma unroll
        for (int j=0;j<4;j++) Oacc[i][j]=0.f;
    float lacc[2]={0.f,0.f};

    for (int t=0;t<32;t++){
        float cp[2][2];
        #pragma unroll
        for (int r=0;r<2;r++){
            const float* yp=ryg+((size_t)bh*NQ+qc[r])*64+2*t;
            cp[r][0]=(yp[0]-shift[r])*L2E;
            cp[r][1]=(yp[1]-shift[r])*L2E;
        }
        unsigned mbw[4];
        #pragma unroll
        for (int j=0;j<4;j++) mbw[j]=mbits[b*128+t*4+j];

        #pragma unroll
        for (int ks=0;ks<8;ks++){
            const int kt16=t*8+ks;
            float sc[2][4];
            #pragma unroll
            for (int j=0;j<2;j++)
                #pragma unroll
                for (int i=0;i<4;i++) sc[j][i]=0.f;
            #pragma unroll
            for (int j=0;j<2;j++){
                const uint2* kf=KfB+(size_t)(2*kt16+j)*64+lane;
                mma16816(sc[j], qf[0], kf[0]);
                mma16816(sc[j], qf[1], kf[32]);
            }
            // exp + pack P a-fragment
            float pv[2][4];
            const int yp=ks>>2;
            #pragma unroll
            for (int j=0;j<2;j++){
                const int nt=2*ks+j;
                #pragma unroll
                for (int i=0;i<4;i++){
                    const int row=i>>1, e=i&1;
                    float madd=(mbw[nt>>2]&(1u<<((nt&3)*8+tg*2+e)))?-100.f:0.f;
                    float s=sc[j][i]+rxv[row][(nt&7)*2+e]+madd;
                    float p=ex2f(fmaf(s,L2E,cp[row][yp]));
                    pv[j][i]=p;
                    lacc[row]+=p;
                }
            }
            uint32_t pa[4];
            pa[0]=pack_h2(pv[0][0],pv[0][1]);
            pa[1]=pack_h2(pv[0][2],pv[0][3]);
            pa[2]=pack_h2(pv[1][0],pv[1][1]);
            pa[3]=pack_h2(pv[1][2],pv[1][3]);
            const uint2* vf=VfB+(size_t)kt16*128+lane;
            #pragma unroll
            for (int nv=0;nv<4;nv++)
                mma16816(Oacc[nv], pa, vf[nv*32]);
        }
    }

    float inv[2];
    #pragma unroll
    for (int r=0;r<2;r++){
        float l=lacc[r];
        l+=__shfl_xor_sync(0xffffffffu,l,1);
        l+=__shfl_xor_sync(0xffffffffu,l,2);
        inv[r]=1.f/l;
    }
    #pragma unroll
    for (int r=0;r<2;r++){
        if (qr[r]<NQ){
            float* dst=ao+((size_t)b*NQ+qr[r])*CC+h*32;
            #pragma unroll
            for (int nv=0;nv<4;nv++){
                float2 o;
                o.x=Oacc[nv][2*r]*inv[r];
                o.y=Oacc[nv][2*r+1]*inv[r];
                *(float2*)&dst[nv*8+tg*2]=o;
            }
        }
    }
}

// wait: C fragment rows: c0,c1 -> row g; c2,c3 -> row g+8. In exp loop row=i>>1
// maps i=0,1 -> row 0 (g) and i=2,3 -> row 1 (g+8): consistent with Oacc use above.

// ---------------- launch ----------------
extern "C" void kernel_launch(void* const* d_in, const int* in_sizes, int n_in,
                              void* d_out, int out_size)
{
    const float* query=(const float*)d_in[1];
    const float* ref  =(const float*)d_in[2];
    const float* kin  =(const float*)d_in[3];
    const float* vin  =(const float*)d_in[4];
    const unsigned char* mask=(const unsigned char*)d_in[6];
    const float* W1x=(const float*)d_in[7];
    const float* b1x=(const float*)d_in[8];
    const float* W2x=(const float*)d_in[9];
    const float* W1y=(const float*)d_in[10];
    const float* b1y=(const float*)d_in[11];
    const float* W2y=(const float*)d_in[12];
    const float* Wq =(const float*)d_in[13];
    const float* bq =(const float*)d_in[14];
    const float* Wk =(const float*)d_in[15];
    const float* bk =(const float*)d_in[16];
    const float* Wv =(const float*)d_in[17];
    const float* bv =(const float*)d_in[18];
    const float* Wp =(const float*)d_in[19];
    const float* bp =(const float*)d_in[20];
    float* out=(float*)d_out;

    void *pq,*pk,*pv,*pkf,*pvf,*pmb,*prx,*pry,*pao;
    cudaGetSymbolAddress(&pq, g_q);
    cudaGetSymbolAddress(&pk, g_k);
    cudaGetSymbolAddress(&pv, g_v);
    cudaGetSymbolAddress(&pkf,g_kf);
    cudaGetSymbolAddress(&pvf,g_vf);
    cudaGetSymbolAddress(&pmb,g_mb);
    cudaGetSymbolAddress(&prx,g_rx);
    cudaGetSymbolAddress(&pry,g_ry);
    cudaGetSymbolAddress(&pao,g_ao);

    const float scale=0.17677669529663687f;
    const int MQ=BB*NQ, MK=BB*NN;

    gemm256_kernel<<<dim3(4,(MQ+63)/64),256>>>(query,Wq,bq,(float*)pq,MQ,scale);
    gemm256_kernel<<<dim3(4,MK/64),256>>>(kin,Wk,bk,(float*)pk,MK,1.0f);
    gemm256_kernel<<<dim3(4,MK/64),256>>>(vin,Wv,bv,(float*)pv,MK,1.0f);

    pack_kf_kernel<<<BB*HH*512*2*32/256,256>>>((const float*)pk,(uint2*)pkf);
    pack_vf_kernel<<<BB*HH*256*4*32/256,256>>>((const float*)pv,(uint2*)pvf);
    pack_mask_kernel<<<1,256>>>(mask,(unsigned*)pmb);

    rpe_kernel<<<MQ,256>>>(ref,W1x,b1x,W2x,W1y,b1y,W2y,(float*)prx,(float*)pry);

    attn_hmma_kernel<<<dim3(8,BB*HH),256>>>(
        (const float*)pq,(const uint2*)pkf,(const uint2*)pvf,
        (const float*)prx,(const float*)pry,(const unsigned*)pmb,(float*)pao);

    gemm256_kernel<<<dim3(4,(MQ+63)/64),256>>>((const float*)pao,Wp,bp,out,MQ,1.0f);
}

// round 5
// speedup vs baseline: 2.5647x; 1.3891x over previous
#include <cuda_runtime.h>
#include <cuda_fp16.h>
#include <cstdint>

#define BB 2
#define NQ 900
#define CC 256
#define HH 8
#define NN 4096
#define DH 32

// -------- scratch --------
__device__ float  g_q  [BB*NQ*CC];          // scaled Q projection fp32
__device__ __half g_qah[BB*NQ*CC];          // query fp16
__device__ __half g_kah[BB*NN*CC];          // kin fp16
__device__ __half g_vah[BB*NN*CC];          // vin fp16
__device__ __half g_kh [BB*NN*CC];          // K projection fp16 row-major
__device__ __half g_vh [BB*NN*CC];          // V projection fp16 row-major
__device__ uint2  g_wqf[16384], g_wkf[16384], g_wvf[16384];
__device__ uint2  g_wpfh[16384], g_wpfl[16384];
__device__ uint2  g_w2fh[2048], g_w2fl[2048];
__device__ uint2  g_kf[BB*HH*512*2*32];
__device__ uint2  g_vf[BB*HH*256*4*32];
__device__ unsigned g_mb[BB*128];
__device__ float  g_rx[BB*HH*NQ*64];
__device__ float  g_ry[BB*HH*NQ*64];
__device__ float  g_ao[BB*NQ*CC];
__device__ __half g_aoh[BB*NQ*CC];
__device__ __half g_aol[BB*NQ*CC];

__device__ __forceinline__ uint32_t pack_h2(float lo, float hi){
    uint32_t r; asm("cvt.rn.f16x2.f32 %0, %1, %2;" : "=r"(r) : "f"(hi), "f"(lo)); return r;
}
__device__ __forceinline__ float lo_f(uint32_t x){ return __low2float(*(__half2*)&x); }
__device__ __forceinline__ float hi_f(uint32_t x){ return __high2float(*(__half2*)&x); }
__device__ __forceinline__ float ex2f(float x){ float r; asm("ex2.approx.f32 %0, %1;":"=f"(r):"f"(x)); return r; }
__device__ __forceinline__ void mma16816(float* c, const uint32_t* a, uint2 b){
    asm volatile("mma.sync.aligned.m16n8k16.row.col.f32.f16.f16.f32 "
      "{%0,%1,%2,%3}, {%4,%5,%6,%7}, {%8,%9}, {%0,%1,%2,%3};"
      : "+f"(c[0]),"+f"(c[1]),"+f"(c[2]),"+f"(c[3])
      : "r"(a[0]),"r"(a[1]),"r"(a[2]),"r"(a[3]),"r"(b.x),"r"(b.y));
}

// ---------------- elementwise packs ----------------
__global__ void f2h_kernel(const float* __restrict__ in, __half* __restrict__ out, int n2){
    int i=blockIdx.x*256+threadIdx.x;
    if (i<n2){ float2 v=*(const float2*)&in[i*2]; *(__half2*)&out[i*2]=__floats2half2_rn(v.x,v.y); }
}
__global__ void pack_ao_kernel(const float* __restrict__ in, __half* __restrict__ oh,
                               __half* __restrict__ ol, int n){
    int i=blockIdx.x*256+threadIdx.x;
    if (i<n){
        float v=in[i];
        __half h=__float2half_rn(v);
        oh[i]=h; ol[i]=__float2half_rn(v-__half2float(h));
    }
}
// W[256,256] row-major [k][n] -> B-fragments [n8(32)][ks(16)][lane] (+optional lo)
__global__ void packW_kernel(const float* __restrict__ W, uint2* __restrict__ fh, uint2* __restrict__ fl){
    int idx=blockIdx.x*256+threadIdx.x;  // 16384
    int lane=idx&31, ks=(idx>>5)&15, n8=idx>>9;
    int k0=ks*16+(lane&3)*2, n=n8*8+(lane>>2);
    float w00=W[k0*256+n], w01=W[(k0+1)*256+n], w08=W[(k0+8)*256+n], w09=W[(k0+9)*256+n];
    uint2 hi=make_uint2(pack_h2(w00,w01), pack_h2(w08,w09));
    fh[idx]=hi;
    if (fl){
        fl[idx]=make_uint2(pack_h2(w00-lo_f(hi.x), w01-hi_f(hi.x)),
                           pack_h2(w08-lo_f(hi.y), w09-hi_f(hi.y)));
    }
}
// W2[512,8] -> frags [axis][ks(32)][lane], hi+lo
__global__ void packW2_kernel(const float* __restrict__ W2x, const float* __restrict__ W2y,
                              uint2* __restrict__ fh, uint2* __restrict__ fl){
    int idx=blockIdx.x*256+threadIdx.x;  // 2048
    int axis=idx>>10, r=idx&1023, lane=r&31, ks=r>>5;
    int j0=ks*16+(lane&3)*2, h=lane>>2;
    const float* W2=axis?W2y:W2x;
    float w00=W2[j0*8+h], w01=W2[(j0+1)*8+h], w08=W2[(j0+8)*8+h], w09=W2[(j0+9)*8+h];
    uint2 hi=make_uint2(pack_h2(w00,w01), pack_h2(w08,w09));
    fh[idx]=hi;
    fl[idx]=make_uint2(pack_h2(w00-lo_f(hi.x), w01-hi_f(hi.x)),
                       pack_h2(w08-lo_f(hi.y), w09-hi_f(hi.y)));
}

// ---------------- HMMA GEMM: out[M,256] = A@W + bias ----------------
// CTA 64x64, 8 warps (4 row-tiles x 2 col-halves), warp 16x32.
__global__ __launch_bounds__(256) void gemm_h_kernel(
    const __half* __restrict__ A, const uint2* __restrict__ Wf,
    const float* __restrict__ bias, float* __restrict__ outf,
    __half* __restrict__ outh, int M, float scale)
{
    const int tid=threadIdx.x, wid=tid>>5, lane=tid&31;
    const int g=lane>>2, tg=lane&3;
    const int wrow=wid>>1, wcol=wid&1;
    const int bm=blockIdx.y*64, bn=blockIdx.x*64;
    const int r0=bm+wrow*16+g, r1=r0+8;
    const int r0c=r0<M?r0:M-1, r1c=r1<M?r1:M-1;
    const uint2* wf=Wf+((bn>>3)+wcol*4)*512+lane;
    float c[4][4]={};
    #pragma unroll
    for (int ks=0;ks<16;ks++){
        const int k0=ks*16+tg*2;
        uint32_t a[4];
        a[0]=*(const uint32_t*)&A[r0c*256+k0];
        a[1]=*(const uint32_t*)&A[r1c*256+k0];
        a[2]=*(const uint32_t*)&A[r0c*256+k0+8];
        a[3]=*(const uint32_t*)&A[r1c*256+k0+8];
        #pragma unroll
        for (int nt=0;nt<4;nt++) mma16816(c[nt], a, wf[nt*512+ks*32]);
    }
    const int cn=bn+wcol*32;
    #pragma unroll
    for (int nt=0;nt<4;nt++){
        int col=cn+nt*8+tg*2;
        float b0=bias[col], b1=bias[col+1];
        if (outh){
            if (r0<M) *(__half2*)&outh[r0*256+col]=__floats2half2_rn(c[nt][0]+b0,c[nt][1]+b1);
            if (r1<M) *(__half2*)&outh[r1*256+col]=__floats2half2_rn(c[nt][2]+b0,c[nt][3]+b1);
        } else {
            if (r0<M){ float2 o=make_float2((c[nt][0]+b0)*scale,(c[nt][1]+b1)*scale); *(float2*)&outf[r0*256+col]=o; }
            if (r1<M){ float2 o=make_float2((c[nt][2]+b0)*scale,(c[nt][3]+b1)*scale); *(float2*)&outf[r1*256+col]=o; }
        }
    }
}

// 3-term split GEMM for output projection (fp32 out)
__global__ __launch_bounds__(256) void gemm_h3_kernel(
    const __half* __restrict__ Ah, const __half* __restrict__ Al,
    const uint2* __restrict__ Wfh, const uint2* __restrict__ Wfl,
    const float* __restrict__ bias, float* __restrict__ out, int M)
{
    const int tid=threadIdx.x, wid=tid>>5, lane=tid&31;
    const int g=lane>>2, tg=lane&3;
    const int wrow=wid>>1, wcol=wid&1;
    const int bm=blockIdx.y*64, bn=blockIdx.x*64;
    const int r0=bm+wrow*16+g, r1=r0+8;
    const int r0c=r0<M?r0:M-1, r1c=r1<M?r1:M-1;
    const int fbase=((bn>>3)+wcol*4)*512+lane;
    float c[4][4]={};
    #pragma unroll
    for (int ks=0;ks<16;ks++){
        const int k0=ks*16+tg*2;
        uint32_t ah[4], al[4];
        ah[0]=*(const uint32_t*)&Ah[r0c*256+k0];
        ah[1]=*(const uint32_t*)&Ah[r1c*256+k0];
        ah[2]=*(const uint32_t*)&Ah[r0c*256+k0+8];
        ah[3]=*(const uint32_t*)&Ah[r1c*256+k0+8];
        al[0]=*(const uint32_t*)&Al[r0c*256+k0];
        al[1]=*(const uint32_t*)&Al[r1c*256+k0];
        al[2]=*(const uint32_t*)&Al[r0c*256+k0+8];
        al[3]=*(const uint32_t*)&Al[r1c*256+k0+8];
        #pragma unroll
        for (int nt=0;nt<4;nt++){
            uint2 bh=Wfh[fbase+nt*512+ks*32];
            uint2 bl=Wfl[fbase+nt*512+ks*32];
            mma16816(c[nt], ah, bh);
            mma16816(c[nt], ah, bl);
            mma16816(c[nt], al, bh);
        }
    }
    const int cn=bn+wcol*32;
    #pragma unroll
    for (int nt=0;nt<4;nt++){
        int col=cn+nt*8+tg*2;
        float b0=bias[col], b1=bias[col+1];
        if (r0<M){ float2 o=make_float2(c[nt][0]+b0,c[nt][1]+b1); *(float2*)&out[r0*256+col]=o; }
        if (r1<M){ float2 o=make_float2(c[nt][2]+b0,c[nt][3]+b1); *(float2*)&out[r1*256+col]=o; }
    }
}

// ---------------- attention fragment packs (fp16 in) ----------------
__global__ __launch_bounds__(256) void pack_kf_kernel(
    const __half* __restrict__ kh, uint2* __restrict__ Kf)
{
    int idx=blockIdx.x*256+threadIdx.x;
    int lane=idx&31, ds=(idx>>5)&1, kt8=(idx>>6)&511, bh=idx>>15;
    int b=bh>>3, h=bh&7;
    int key=kt8*8+(lane>>2), d0=ds*16+(lane&3)*2;
    const __half* src=kh+((size_t)b*NN+key)*CC+h*32+d0;
    Kf[idx]=make_uint2(*(const uint32_t*)src, *(const uint32_t*)(src+8));
}
__global__ __launch_bounds__(256) void pack_vf_kernel(
    const __half* __restrict__ vh, uint2* __restrict__ Vf)
{
    int idx=blockIdx.x*256+threadIdx.x;
    int lane=idx&31, nt=(idx>>5)&3, kt16=(idx>>7)&255, bh=idx>>15;
    int b=bh>>3, h=bh&7;
    int key0=kt16*16+(lane&3)*2, d=nt*8+(lane>>2);
    const __half* src=vh+((size_t)b*NN+key0)*CC+h*32+d;
    __half2 x=__halves2half2(src[0],src[CC]);
    __half2 y=__halves2half2(src[8*CC],src[9*CC]);
    Vf[idx]=make_uint2(*(uint32_t*)&x, *(uint32_t*)&y);
}
__global__ void pack_mask_kernel(const unsigned char* __restrict__ m, unsigned* __restrict__ mb)
{
    int idx=blockIdx.x*256+threadIdx.x;
    if (idx < BB*128){
        const unsigned char* p=m+idx*32;
        unsigned v=0;
        #pragma unroll
        for (int i=0;i<32;i++) v |= (p[i]?1u:0u)<<i;
        mb[idx]=v;
    }
}

// ---------------- RPE via HMMA (alpha/beta + hi/lo split) ----------------
__global__ __launch_bounds__(256) void rpe_hmma_kernel(
    const float* __restrict__ ref,
    const float* __restrict__ W1x, const float* __restrict__ b1x,
    const float* __restrict__ W1y, const float* __restrict__ b1y,
    const uint2* __restrict__ w2fh, const uint2* __restrict__ w2fl,
    float* __restrict__ rx, float* __restrict__ ry)
{
    __shared__ float2 sAB[2][512];
    const int bq=blockIdx.x, b=bq/NQ, q=bq-b*NQ, tid=threadIdx.x;
    float4 box=*(const float4*)&ref[bq*4];
    float lox=box.x-box.z*0.5f, hix=box.x+box.z*0.5f;
    float loy=box.y-box.w*0.5f, hiy=box.y+box.w*0.5f;
    for (int idx=tid; idx<1024; idx+=256){
        int axis=idx>>9, j=idx&511;
        const float* W1=axis?W1y:W1x;
        float u=W1[j], v=W1[512+j];
        float bb=(axis?b1y:b1x)[j];
        float LO=axis?loy:lox, HI=axis?hiy:hix;
        sAB[axis][j]=make_float2(fmaf(LO,u,fmaf(HI,v,bb)), u+v);
    }
    __syncthreads();
    const int wid=tid>>5, lane=tid&31, g=lane>>2, tg=lane&3;
    const int axis=wid>>2, mt=wid&3;
    const float p0=((float)(mt*16+g)+0.5f)*16.f;
    const float p1=p0+128.f;
    const uint2* fh=w2fh+axis*1024+lane;
    const uint2* fl=w2fl+axis*1024+lane;
    const float2* AB=sAB[axis];
    float c[4]={0.f,0.f,0.f,0.f};
    #pragma unroll 4
    for (int ks=0;ks<32;ks++){
        int j0=ks*16+tg*2;
        float2 ab0=AB[j0], ab1=AB[j0+1], ab8=AB[j0+8], ab9=AB[j0+9];
        float h00=fmaxf(fmaf(-p0,ab0.y,ab0.x),0.f);
        float h01=fmaxf(fmaf(-p0,ab1.y,ab1.x),0.f);
        float h10=fmaxf(fmaf(-p1,ab0.y,ab0.x),0.f);
        float h11=fmaxf(fmaf(-p1,ab1.y,ab1.x),0.f);
        float h08=fmaxf(fmaf(-p0,ab8.y,ab8.x),0.f);
        float h09=fmaxf(fmaf(-p0,ab9.y,ab9.x),0.f);
        float h18=fmaxf(fmaf(-p1,ab8.y,ab8.x),0.f);
        float h19=fmaxf(fmaf(-p1,ab9.y,ab9.x),0.f);
        uint32_t ah[4], al[4];
        ah[0]=pack_h2(h00,h01); ah[1]=pack_h2(h10,h11);
        ah[2]=pack_h2(h08,h09); ah[3]=pack_h2(h18,h19);
        al[0]=pack_h2(h00-lo_f(ah[0]), h01-hi_f(ah[0]));
        al[1]=pack_h2(h10-lo_f(ah[1]), h11-hi_f(ah[1]));
        al[2]=pack_h2(h08-lo_f(ah[2]), h09-hi_f(ah[2]));
        al[3]=pack_h2(h18-lo_f(ah[3]), h19-hi_f(ah[3]));
        uint2 bh=fh[ks*32], bl=fl[ks*32];
        mma16816(c, ah, bh);
        mma16816(c, ah, bl);
        mma16816(c, al, bh);
    }
    float* outp=axis?ry:rx;
    const int h2=tg*2, pos0=mt*16+g;
    size_t base0=((size_t)(b*8+h2)*NQ+q)*64;
    size_t base1=((size_t)(b*8+h2+1)*NQ+q)*64;
    outp[base0+pos0]=c[0];
    outp[base1+pos0]=c[1];
    outp[base0+pos0+8]=c[2];
    outp[base1+pos0+8]=c[3];
}

// ---------------- HMMA flash attention (validated round 4) ----------------
__global__ __launch_bounds__(256) void attn_hmma_kernel(
    const float* __restrict__ qp, const uint2* __restrict__ Kf, const uint2* __restrict__ Vf,
    const float* __restrict__ rxg, const float* __restrict__ ryg,
    const unsigned* __restrict__ mbits, float* __restrict__ ao)
{
    const int tid=threadIdx.x, wid=tid>>5, lane=tid&31;
    const int g=lane>>2, tg=lane&3;
    const int bh=blockIdx.y, b=bh>>3, h=bh&7;
    const int q0=blockIdx.x*128 + wid*16;
    const float L2E=1.4426950408889634f;
    int qr[2]={q0+g, q0+g+8};
    int qc[2]={qr[0]<NQ?qr[0]:NQ-1, qr[1]<NQ?qr[1]:NQ-1};

    uint32_t qf[2][4];
    #pragma unroll
    for (int ds=0;ds<2;ds++)
        #pragma unroll
        for (int r=0;r<2;r++){
            const float* p=qp+((size_t)b*NQ+qc[r])*CC+h*32+ds*16+tg*2;
            qf[ds][r]  =pack_h2(p[0],p[1]);
            qf[ds][r+2]=pack_h2(p[8],p[9]);
        }

    float rxv[2][16], shift[2];
    #pragma unroll
    for (int r=0;r<2;r++){
        const float* rp=rxg+((size_t)bh*NQ+qc[r])*64;
        float mx=-1e30f;
        #pragma unroll
        for (int j=0;j<8;j++){
            float2 v=*(const float2*)&rp[j*8+tg*2];
            rxv[r][j*2]=v.x; rxv[r][j*2+1]=v.y;
            mx=fmaxf(mx,fmaxf(v.x,v.y));
        }
        mx=fmaxf(mx,__shfl_xor_sync(0xffffffffu,mx,1));
        mx=fmaxf(mx,__shfl_xor_sync(0xffffffffu,mx,2));
        const float* yp=ryg+((size_t)bh*NQ+qc[r])*64;
        float my=-1e30f;
        #pragma unroll
        for (int j=0;j<16;j++) my=fmaxf(my,yp[tg+4*j]);
        my=fmaxf(my,__shfl_xor_sync(0xffffffffu,my,1));
        my=fmaxf(my,__shfl_xor_sync(0xffffffffu,my,2));
        shift[r]=mx+my;
    }

    const uint2* KfB=Kf+(size_t)bh*32768;
    const uint2* VfB=Vf+(size_t)bh*32768;
    float Oacc[4][4];
    #pragma unroll
    for (int i=0;i<4;i++)
        #pragma unroll
        for (int j=0;j<4;j++) Oacc[i][j]=0.f;
    float lacc[2]={0.f,0.f};

    for (int t=0;t<32;t++){
        float cp[2][2];
        #pragma unroll
        for (int r=0;r<2;r++){
            const float* yp=ryg+((size_t)bh*NQ+qc[r])*64+2*t;
            cp[r][0]=(yp[0]-shift[r])*L2E;
            cp[r][1]=(yp[1]-shift[r])*L2E;
        }
        unsigned mbw[4];
        #pragma unroll
        for (int j=0;j<4;j++) mbw[j]=mbits[b*128+t*4+j];

        #pragma unroll
        for (int ks=0;ks<8;ks++){
            const int kt16=t*8+ks;
            float sc[2][4];
            #pragma unroll
            for (int j=0;j<2;j++)
                #pragma unroll
                for (int i=0;i<4;i++) sc[j][i]=0.f;
            #pragma unroll
            for (int j=0;j<2;j++){
                const uint2* kf=KfB+(size_t)(2*kt16+j)*64+lane;
                mma16816(sc[j], qf[0], kf[0]);
                mma16816(sc[j], qf[1], kf[32]);
            }
            float pv[2][4];
            const int yp=ks>>2;
            #pragma unroll
            for (int j=0;j<2;j++){
                const int nt=2*ks+j;
                #pragma unroll
                for (int i=0;i<4;i++){
                    const int row=i>>1, e=i&1;
                    float madd=(mbw[nt>>2]&(1u<<((nt&3)*8+tg*2+e)))?-100.f:0.f;
                    float s=sc[j][i]+rxv[row][(nt&7)*2+e]+madd;
                    float p=ex2f(fmaf(s,L2E,cp[row][yp]));
                    pv[j][i]=p;
                    lacc[row]+=p;
                }
            }
            uint32_t pa[4];
            pa[0]=pack_h2(pv[0][0],pv[0][1]);
            pa[1]=pack_h2(pv[0][2],pv[0][3]);
            pa[2]=pack_h2(pv[1][0],pv[1][1]);
            pa[3]=pack_h2(pv[1][2],pv[1][3]);
            const uint2* vf=VfB+(size_t)kt16*128+lane;
            #pragma unroll
            for (int nv=0;nv<4;nv++)
                mma16816(Oacc[nv], pa, vf[nv*32]);
        }
    }

    float inv[2];
    #pragma unroll
    for (int r=0;r<2;r++){
        float l=lacc[r];
        l+=__shfl_xor_sync(0xffffffffu,l,1);
        l+=__shfl_xor_sync(0xffffffffu,l,2);
        inv[r]=1.f/l;
    }
    #pragma unroll
    for (int r=0;r<2;r++){
        if (qr[r]<NQ){
            float* dst=ao+((size_t)b*NQ+qr[r])*CC+h*32;
            #pragma unroll
            for (int nv=0;nv<4;nv++){
                float2 o;
                o.x=Oacc[nv][2*r]*inv[r];
                o.y=Oacc[nv][2*r+1]*inv[r];
                *(float2*)&dst[nv*8+tg*2]=o;
            }
        }
    }
}

// ---------------- launch ----------------
extern "C" void kernel_launch(void* const* d_in, const int* in_sizes, int n_in,
                              void* d_out, int out_size)
{
    const float* query=(const float*)d_in[1];
    const float* ref  =(const float*)d_in[2];
    const float* kin  =(const float*)d_in[3];
    const float* vin  =(const float*)d_in[4];
    const unsigned char* mask=(const unsigned char*)d_in[6];
    const float* W1x=(const float*)d_in[7];
    const float* b1x=(const float*)d_in[8];
    const float* W2x=(const float*)d_in[9];
    const float* W1y=(const float*)d_in[10];
    const float* b1y=(const float*)d_in[11];
    const float* W2y=(const float*)d_in[12];
    const float* Wq =(const float*)d_in[13];
    const float* bq =(const float*)d_in[14];
    const float* Wk =(const float*)d_in[15];
    const float* bk =(const float*)d_in[16];
    const float* Wv =(const float*)d_in[17];
    const float* bv =(const float*)d_in[18];
    const float* Wp =(const float*)d_in[19];
    const float* bp =(const float*)d_in[20];
    float* out=(float*)d_out;

    void *pq,*pqa,*pka,*pva,*pkh,*pvh,*pwq,*pwk,*pwv,*pwph,*pwpl,*pw2h,*pw2l;
    void *pkf,*pvf,*pmb,*prx,*pry,*pao,*paoh,*paol;
    cudaGetSymbolAddress(&pq,  g_q);
    cudaGetSymbolAddress(&pqa, g_qah);
    cudaGetSymbolAddress(&pka, g_kah);
    cudaGetSymbolAddress(&pva, g_vah);
    cudaGetSymbolAddress(&pkh, g_kh);
    cudaGetSymbolAddress(&pvh, g_vh);
    cudaGetSymbolAddress(&pwq, g_wqf);
    cudaGetSymbolAddress(&pwk, g_wkf);
    cudaGetSymbolAddress(&pwv, g_wvf);
    cudaGetSymbolAddress(&pwph,g_wpfh);
    cudaGetSymbolAddress(&pwpl,g_wpfl);
    cudaGetSymbolAddress(&pw2h,g_w2fh);
    cudaGetSymbolAddress(&pw2l,g_w2fl);
    cudaGetSymbolAddress(&pkf, g_kf);
    cudaGetSymbolAddress(&pvf, g_vf);
    cudaGetSymbolAddress(&pmb, g_mb);
    cudaGetSymbolAddress(&prx, g_rx);
    cudaGetSymbolAddress(&pry, g_ry);
    cudaGetSymbolAddress(&pao, g_ao);
    cudaGetSymbolAddress(&paoh,g_aoh);
    cudaGetSymbolAddress(&paol,g_aol);

    const float scale=0.17677669529663687f;
    const int MQ=BB*NQ, MK=BB*NN;

    // input fp16 packs
    f2h_kernel<<<(MQ*CC/2+255)/256,256>>>(query,(__half*)pqa,MQ*CC/2);
    f2h_kernel<<<(MK*CC/2+255)/256,256>>>(kin,(__half*)pka,MK*CC/2);
    f2h_kernel<<<(MK*CC/2+255)/256,256>>>(vin,(__half*)pva,MK*CC/2);
    // weight fragment packs
    packW_kernel<<<64,256>>>(Wq,(uint2*)pwq,nullptr);
    packW_kernel<<<64,256>>>(Wk,(uint2*)pwk,nullptr);
    packW_kernel<<<64,256>>>(Wv,(uint2*)pwv,nullptr);
    packW_kernel<<<64,256>>>(Wp,(uint2*)pwph,(uint2*)pwpl);
    packW2_kernel<<<8,256>>>(W2x,W2y,(uint2*)pw2h,(uint2*)pw2l);
    pack_mask_kernel<<<1,256>>>(mask,(unsigned*)pmb);

    // projections (HMMA)
    gemm_h_kernel<<<dim3(4,(MQ+63)/64),256>>>((const __half*)pqa,(const uint2*)pwq,bq,(float*)pq,nullptr,MQ,scale);
    gemm_h_kernel<<<dim3(4,MK/64),256>>>((const __half*)pka,(const uint2*)pwk,bk,nullptr,(__half*)pkh,MK,1.f);
    gemm_h_kernel<<<dim3(4,MK/64),256>>>((const __half*)pva,(const uint2*)pwv,bv,nullptr,(__half*)pvh,MK,1.f);

    pack_kf_kernel<<<BB*HH*512*2*32/256,256>>>((const __half*)pkh,(uint2*)pkf);
    pack_vf_kernel<<<BB*HH*256*4*32/256,256>>>((const __half*)pvh,(uint2*)pvf);

    rpe_hmma_kernel<<<MQ,256>>>(ref,W1x,b1x,W1y,b1y,(const uint2*)pw2h,(const uint2*)pw2l,(float*)prx,(float*)pry);

    attn_hmma_kernel<<<dim3(8,BB*HH),256>>>(
        (const float*)pq,(const uint2*)pkf,(const uint2*)pvf,
        (const float*)prx,(const float*)pry,(const unsigned*)pmb,(float*)pao);

    pack_ao_kernel<<<(MQ*CC+255)/256,256>>>((const float*)pao,(__half*)paoh,(__half*)paol,MQ*CC);
    gemm_h3_kernel<<<dim3(4,(MQ+63)/64),256>>>((const __half*)paoh,(const __half*)paol,
        (const uint2*)pwph,(const uint2*)pwpl,bp,out,MQ);
}

// round 7
// speedup vs baseline: 4.0624x; 1.5840x over previous
#include <cuda_runtime.h>
#include <cuda_fp16.h>
#include <cstdint>

#define BB 2
#define NQ 900
#define CC 256
#define HH 8
#define NN 4096
#define DH 32

// -------- scratch --------
__device__ float  g_q  [BB*NQ*CC];          // scaled Q projection (scale*log2e)
__device__ __half g_qah[BB*NQ*CC];
__device__ __half g_kah[BB*NN*CC];
__device__ __half g_vah[BB*NN*CC];
__device__ __half g_kh [BB*NN*CC];
__device__ __half g_vh [BB*NN*CC];
__device__ uint2  g_wqf[16384], g_wkf[16384], g_wvf[16384];
__device__ uint2  g_wpfh[16384], g_wpfl[16384];
__device__ uint2  g_w2fh[2048], g_w2fl[2048];
__device__ uint2  g_kf[BB*HH*512*2*32];
__device__ uint2  g_vf[BB*HH*256*4*32];
__device__ unsigned g_mb[BB*128];
__device__ float  g_rx[BB*HH*NQ*64];        // scaled by log2e
__device__ float  g_ry[BB*HH*NQ*64];        // scaled by log2e
__device__ float  g_aop[2*BB*NQ*CC];        // raw partial O (ksplit halves)
__device__ float  g_lp [2*BB*HH*NQ];        // partial l
__device__ __half g_aoh[BB*NQ*CC];
__device__ __half g_aol[BB*NQ*CC];

__device__ __forceinline__ uint32_t pack_h2(float lo, float hi){
    uint32_t r; asm("cvt.rn.f16x2.f32 %0, %1, %2;" : "=r"(r) : "f"(hi), "f"(lo)); return r;
}
__device__ __forceinline__ float lo_f(uint32_t x){ return __low2float(*(__half2*)&x); }
__device__ __forceinline__ float hi_f(uint32_t x){ return __high2float(*(__half2*)&x); }
__device__ __forceinline__ float ex2f(float x){ float r; asm("ex2.approx.f32 %0, %1;":"=f"(r):"f"(x)); return r; }
__device__ __forceinline__ void mma16816(float* c, const uint32_t* a, uint2 b){
    asm volatile("mma.sync.aligned.m16n8k16.row.col.f32.f16.f16.f32 "
      "{%0,%1,%2,%3}, {%4,%5,%6,%7}, {%8,%9}, {%0,%1,%2,%3};"
      : "+f"(c[0]),"+f"(c[1]),"+f"(c[2]),"+f"(c[3])
      : "r"(a[0]),"r"(a[1]),"r"(a[2]),"r"(a[3]),"r"(b.x),"r"(b.y));
}

#define L2E 1.4426950408889634f

// =================================================================
// Launch 0: mega prep (f2h x3, packW x4, packW2, mask)
// =================================================================
__global__ __launch_bounds__(256) void prep_kernel(
    const float* __restrict__ query, const float* __restrict__ kin, const float* __restrict__ vin,
    const float* __restrict__ Wq, const float* __restrict__ Wk, const float* __restrict__ Wv,
    const float* __restrict__ Wp, const float* __restrict__ W2x, const float* __restrict__ W2y,
    const unsigned char* __restrict__ mask,
    __half* __restrict__ qah, __half* __restrict__ kah, __half* __restrict__ vah,
    uint2* __restrict__ wqf, uint2* __restrict__ wkf, uint2* __restrict__ wvf,
    uint2* __restrict__ wpfh, uint2* __restrict__ wpfl,
    uint2* __restrict__ w2fh, uint2* __restrict__ w2fl, unsigned* __restrict__ mb)
{
    const int blk=blockIdx.x, tid=threadIdx.x;
    if (blk < 9092){
        const float* in; __half* out; int i;
        if (blk < 900){ in=query; out=qah; i=blk*256+tid; }
        else if (blk < 4996){ in=kin; out=kah; i=(blk-900)*256+tid; }
        else { in=vin; out=vah; i=(blk-4996)*256+tid; }
        float2 v=*(const float2*)&in[i*2];
        *(__half2*)&out[i*2]=__floats2half2_rn(v.x,v.y);
        return;
    }
    if (blk < 9348){
        const float* W; uint2 *fh, *fl=nullptr;
        int base;
        if (blk < 9156){ W=Wq; fh=wqf; base=9092; }
        else if (blk < 9220){ W=Wk; fh=wkf; base=9156; }
        else if (blk < 9284){ W=Wv; fh=wvf; base=9220; }
        else { W=Wp; fh=wpfh; fl=wpfl; base=9284; }
        int idx=(blk-base)*256+tid;
        int lane=idx&31, ks=(idx>>5)&15, n8=idx>>9;
        int k0=ks*16+(lane&3)*2, n=n8*8+(lane>>2);
        float w00=W[k0*256+n], w01=W[(k0+1)*256+n], w08=W[(k0+8)*256+n], w09=W[(k0+9)*256+n];
        uint2 hi=make_uint2(pack_h2(w00,w01), pack_h2(w08,w09));
        fh[idx]=hi;
        if (fl) fl[idx]=make_uint2(pack_h2(w00-lo_f(hi.x), w01-hi_f(hi.x)),
                                   pack_h2(w08-lo_f(hi.y), w09-hi_f(hi.y)));
        return;
    }
    if (blk < 9356){
        int idx=(blk-9348)*256+tid;
        int axis=idx>>10, r=idx&1023, lane=r&31, ks=r>>5;
        int j0=ks*16+(lane&3)*2, h=lane>>2;
        const float* W2=axis?W2y:W2x;
        float w00=W2[j0*8+h], w01=W2[(j0+1)*8+h], w08=W2[(j0+8)*8+h], w09=W2[(j0+9)*8+h];
        uint2 hi=make_uint2(pack_h2(w00,w01), pack_h2(w08,w09));
        w2fh[idx]=hi;
        w2fl[idx]=make_uint2(pack_h2(w00-lo_f(hi.x), w01-hi_f(hi.x)),
                             pack_h2(w08-lo_f(hi.y), w09-hi_f(hi.y)));
        return;
    }
    if (tid < BB*128){
        const unsigned char* p=mask+tid*32;
        unsigned v=0;
        #pragma unroll
        for (int i=0;i<32;i++) v |= (p[i]?1u:0u)<<i;
        mb[tid]=v;
    }
}

// =================================================================
// Launch 1: fused Q/K/V projection GEMM. grid (4, 128, 3)
// =================================================================
__global__ __launch_bounds__(256) void gemm_all_kernel(
    const __half* __restrict__ qa, const __half* __restrict__ ka, const __half* __restrict__ va,
    const uint2* __restrict__ wq, const uint2* __restrict__ wk, const uint2* __restrict__ wv,
    const float* __restrict__ bq, const float* __restrict__ bk, const float* __restrict__ bv,
    float* __restrict__ qout, __half* __restrict__ kh, __half* __restrict__ vh, float qscale)
{
    const int z=blockIdx.z;
    const __half* A; const uint2* Wf; const float* bias; int M;
    if (z==0){ A=qa; Wf=wq; bias=bq; M=BB*NQ; }
    else if (z==1){ A=ka; Wf=wk; bias=bk; M=BB*NN; }
    else { A=va; Wf=wv; bias=bv; M=BB*NN; }
    const int bm=blockIdx.y*64;
    if (bm >= M) return;
    const int tid=threadIdx.x, wid=tid>>5, lane=tid&31;
    const int g=lane>>2, tg=lane&3;
    const int wrow=wid>>1, wcol=wid&1;
    const int bn=blockIdx.x*64;
    const int r0=bm+wrow*16+g, r1=r0+8;
    const int r0c=r0<M?r0:M-1, r1c=r1<M?r1:M-1;
    const uint2* wf=Wf+((bn>>3)+wcol*4)*512+lane;
    float c[4][4]={};
    #pragma unroll
    for (int ks=0;ks<16;ks++){
        const int k0=ks*16+tg*2;
        uint32_t a[4];
        a[0]=*(const uint32_t*)&A[r0c*256+k0];
        a[1]=*(const uint32_t*)&A[r1c*256+k0];
        a[2]=*(const uint32_t*)&A[r0c*256+k0+8];
        a[3]=*(const uint32_t*)&A[r1c*256+k0+8];
        #pragma unroll
        for (int nt=0;nt<4;nt++) mma16816(c[nt], a, wf[nt*512+ks*32]);
    }
    const int cn=bn+wcol*32;
    #pragma unroll
    for (int nt=0;nt<4;nt++){
        int col=cn+nt*8+tg*2;
        float b0=bias[col], b1=bias[col+1];
        if (z==0){
            if (r0<M){ float2 o=make_float2((c[nt][0]+b0)*qscale,(c[nt][1]+b1)*qscale); *(float2*)&qout[r0*256+col]=o; }
            if (r1<M){ float2 o=make_float2((c[nt][2]+b0)*qscale,(c[nt][3]+b1)*qscale); *(float2*)&qout[r1*256+col]=o; }
        } else {
            __half* outh=(z==1)?kh:vh;
            if (r0<M) *(__half2*)&outh[r0*256+col]=__floats2half2_rn(c[nt][0]+b0,c[nt][1]+b1);
            if (r1<M) *(__half2*)&outh[r1*256+col]=__floats2half2_rn(c[nt][2]+b0,c[nt][3]+b1);
        }
    }
}

// =================================================================
// Launch 2: fused kf-pack [0,2048), vf-pack [2048,4096), rpe [4096,5896)
// =================================================================
__global__ __launch_bounds__(256) void mid_kernel(
    const __half* __restrict__ kh, const __half* __restrict__ vh,
    uint2* __restrict__ Kf, uint2* __restrict__ Vf,
    const float* __restrict__ ref,
    const float* __restrict__ W1x, const float* __restrict__ b1x,
    const float* __restrict__ W1y, const float* __restrict__ b1y,
    const uint2* __restrict__ w2fh, const uint2* __restrict__ w2fl,
    float* __restrict__ rx, float* __restrict__ ry)
{
    const int blk=blockIdx.x, tid=threadIdx.x;
    if (blk < 2048){
        int idx=blk*256+tid;
        int lane=idx&31, ds=(idx>>5)&1, kt8=(idx>>6)&511, bh=idx>>15;
        int b=bh>>3, h=bh&7;
        int key=kt8*8+(lane>>2), d0=ds*16+(lane&3)*2;
        const __half* src=kh+((size_t)b*NN+key)*CC+h*32+d0;
        Kf[idx]=make_uint2(*(const uint32_t*)src, *(const uint32_t*)(src+8));
        return;
    }
    if (blk < 4096){
        int idx=(blk-2048)*256+tid;
        int lane=idx&31, nt=(idx>>5)&3, kt16=(idx>>7)&255, bh=idx>>15;
        int b=bh>>3, h=bh&7;
        int key0=kt16*16+(lane&3)*2, d=nt*8+(lane>>2);
        const __half* src=vh+((size_t)b*NN+key0)*CC+h*32+d;
        __half2 x=__halves2half2(src[0],src[CC]);
        __half2 y=__halves2half2(src[8*CC],src[9*CC]);
        Vf[idx]=make_uint2(*(uint32_t*)&x, *(uint32_t*)&y);
        return;
    }
    // ---- RPE ----
    __shared__ float2 sAB[2][512];
    const int bq=blk-4096, b=bq/NQ, q=bq-b*NQ;
    float4 box=*(const float4*)&ref[bq*4];
    float lox=box.x-box.z*0.5f, hix=box.x+box.z*0.5f;
    float loy=box.y-box.w*0.5f, hiy=box.y+box.w*0.5f;
    for (int idx=tid; idx<1024; idx+=256){
        int axis=idx>>9, j=idx&511;
        const float* W1=axis?W1y:W1x;
        float u=W1[j], v=W1[512+j];
        float bb=(axis?b1y:b1x)[j];
        float LO=axis?loy:lox, HI=axis?hiy:hix;
        sAB[axis][j]=make_float2(fmaf(LO,u,fmaf(HI,v,bb)), u+v);
    }
    __syncthreads();
    const int wid=tid>>5, lane=tid&31, g=lane>>2, tg=lane&3;
    const int axis=wid>>2, mt=wid&3;
    const float p0=((float)(mt*16+g)+0.5f)*16.f;
    const float p1=p0+128.f;
    const uint2* fh=w2fh+axis*1024+lane;
    const uint2* fl=w2fl+axis*1024+lane;
    const float2* AB=sAB[axis];
    float c[4]={0.f,0.f,0.f,0.f};
    #pragma unroll 4
    for (int ks=0;ks<32;ks++){
        int j0=ks*16+tg*2;
        float2 ab0=AB[j0], ab1=AB[j0+1], ab8=AB[j0+8], ab9=AB[j0+9];
        float h00=fmaxf(fmaf(-p0,ab0.y,ab0.x),0.f);
        float h01=fmaxf(fmaf(-p0,ab1.y,ab1.x),0.f);
        float h10=fmaxf(fmaf(-p1,ab0.y,ab0.x),0.f);
        float h11=fmaxf(fmaf(-p1,ab1.y,ab1.x),0.f);
        float h08=fmaxf(fmaf(-p0,ab8.y,ab8.x),0.f);
        float h09=fmaxf(fmaf(-p0,ab9.y,ab9.x),0.f);
        float h18=fmaxf(fmaf(-p1,ab8.y,ab8.x),0.f);
        float h19=fmaxf(fmaf(-p1,ab9.y,ab9.x),0.f);
        uint32_t ah[4], al[4];
        ah[0]=pack_h2(h00,h01); ah[1]=pack_h2(h10,h11);
        ah[2]=pack_h2(h08,h09); ah[3]=pack_h2(h18,h19);
        al[0]=pack_h2(h00-lo_f(ah[0]), h01-hi_f(ah[0]));
        al[1]=pack_h2(h10-lo_f(ah[1]), h11-hi_f(ah[1]));
        al[2]=pack_h2(h08-lo_f(ah[2]), h09-hi_f(ah[2]));
        al[3]=pack_h2(h18-lo_f(ah[3]), h19-hi_f(ah[3]));
        uint2 bh=fh[ks*32], bl=fl[ks*32];
        mma16816(c, ah, bh);
        mma16816(c, ah, bl);
        mma16816(c, al, bh);
    }
    float* outp=axis?ry:rx;
    const int h2=tg*2, pos0=mt*16+g;
    size_t base0=((size_t)(b*8+h2)*NQ+q)*64;
    size_t base1=((size_t)(b*8+h2+1)*NQ+q)*64;
    outp[base0+pos0]    =c[0]*L2E;
    outp[base1+pos0]    =c[1]*L2E;
    outp[base0+pos0+8]  =c[2]*L2E;
    outp[base1+pos0+8]  =c[3]*L2E;
}

// =================================================================
// Launch 3 (PROFILED): HMMA flash attention, 2-way key split.
// =================================================================
__global__ __launch_bounds__(256) void attn_hmma_kernel(
    const float* __restrict__ qp, const uint2* __restrict__ Kf, const uint2* __restrict__ Vf,
    const float* __restrict__ rxg, const float* __restrict__ ryg,
    const unsigned* __restrict__ mbits, float* __restrict__ aop, float* __restrict__ lp)
{
    const int tid=threadIdx.x, wid=tid>>5, lane=tid&31;
    const int g=lane>>2, tg=lane&3;
    const int bh=blockIdx.y, b=bh>>3, h=bh&7;
    const int z=blockIdx.z;
    const int q0=blockIdx.x*128 + wid*16;
    int qr[2]={q0+g, q0+g+8};
    int qc[2]={qr[0]<NQ?qr[0]:NQ-1, qr[1]<NQ?qr[1]:NQ-1};

    uint32_t qf[2][4];
    #pragma unroll
    for (int ds=0;ds<2;ds++)
        #pragma unroll
        for (int r=0;r<2;r++){
            const float* p=qp+((size_t)b*NQ+qc[r])*CC+h*32+ds*16+tg*2;
            qf[ds][r]  =pack_h2(p[0],p[1]);
            qf[ds][r+2]=pack_h2(p[8],p[9]);
        }

    float rxv[2][16], shift[2];
    #pragma unroll
    for (int r=0;r<2;r++){
        const float* rp=rxg+((size_t)bh*NQ+qc[r])*64;
        float mx=-1e30f;
        #pragma unroll
        for (int j=0;j<8;j++){
            float2 v=*(const float2*)&rp[j*8+tg*2];
            rxv[r][j*2]=v.x; rxv[r][j*2+1]=v.y;
            mx=fmaxf(mx,fmaxf(v.x,v.y));
        }
        mx=fmaxf(mx,__shfl_xor_sync(0xffffffffu,mx,1));
        mx=fmaxf(mx,__shfl_xor_sync(0xffffffffu,mx,2));
        const float* yp=ryg+((size_t)bh*NQ+qc[r])*64;
        float my=-1e30f;
        #pragma unroll
        for (int j=0;j<16;j++) my=fmaxf(my,yp[tg+4*j]);
        my=fmaxf(my,__shfl_xor_sync(0xffffffffu,my,1));
        my=fmaxf(my,__shfl_xor_sync(0xffffffffu,my,2));
        shift[r]=mx+my;
    }

    const uint2* KfB=Kf+(size_t)bh*32768;
    const uint2* VfB=Vf+(size_t)bh*32768;
    const uint2 onesb = (lane<4)? make_uint2(0x3C003C00u,0x3C003C00u) : make_uint2(0u,0u);
    float Oacc[4][4];
    #pragma unroll
    for (int i=0;i<4;i++)
        #pragma unroll
        for (int j=0;j<4;j++) Oacc[i][j]=0.f;
    float ls[4]={0.f,0.f,0.f,0.f};

    for (int t=z*16; t<z*16+16; t++){
        float cp0[2][2], cp1[2][2];
        #pragma unroll
        for (int r=0;r<2;r++){
            const float* yp=ryg+((size_t)bh*NQ+qc[r])*64+2*t;
            cp0[r][0]=yp[0]-shift[r];
            cp0[r][1]=yp[1]-shift[r];
            cp1[r][0]=cp0[r][0]-144.26950408889634f;
            cp1[r][1]=cp0[r][1]-144.26950408889634f;
        }
        unsigned mbw[4];
        #pragma unroll
        for (int j=0;j<4;j++) mbw[j]=mbits[b*128+t*4+j];

        #pragma unroll
        for (int ks=0;ks<8;ks++){
            const int kt16=t*8+ks;
            float sc[2][4];
            #pragma unroll
            for (int j=0;j<2;j++)
                #pragma unroll
                for (int i=0;i<4;i++) sc[j][i]=0.f;
            #pragma unroll
            for (int j=0;j<2;j++){
                const uint2* kf=KfB+(size_t)(2*kt16+j)*64+lane;
                mma16816(sc[j], qf[0], kf[0]);
                mma16816(sc[j], qf[1], kf[32]);
            }
            float pv[2][4];
            const int yp=ks>>2;
            #pragma unroll
            for (int j=0;j<2;j++){
                const int nt=2*ks+j;
                #pragma unroll
                for (int i=0;i<4;i++){
                    const int row=i>>1, e=i&1;
                    bool mbit=(mbw[nt>>2]>>((nt&3)*8+tg*2+e))&1u;
                    float s=sc[j][i]+rxv[row][(nt&7)*2+e];
                    float cp=mbit?cp1[row][yp]:cp0[row][yp];
                    pv[j][i]=ex2f(s+cp);
                }
            }
            uint32_t pa[4];
            pa[0]=pack_h2(pv[0][0],pv[0][1]);
            pa[1]=pack_h2(pv[0][2],pv[0][3]);
            pa[2]=pack_h2(pv[1][0],pv[1][1]);
            pa[3]=pack_h2(pv[1][2],pv[1][3]);
            mma16816(ls, pa, onesb);
            const uint2* vf=VfB+(size_t)kt16*128+lane;
            #pragma unroll
            for (int nv=0;nv<4;nv++)
                mma16816(Oacc[nv], pa, vf[nv*32]);
        }
    }

    if (tg==0){
        if (qr[0]<NQ) lp[(size_t)z*BB*HH*NQ + (size_t)bh*NQ + qr[0]] = ls[0];
        if (qr[1]<NQ) lp[(size_t)z*BB*HH*NQ + (size_t)bh*NQ + qr[1]] = ls[2];
    }
    #pragma unroll
    for (int r=0;r<2;r++){
        if (qr[r]<NQ){
            float* dst=aop + (size_t)z*BB*NQ*CC + ((size_t)b*NQ+qr[r])*CC + h*32;
            #pragma unroll
            for (int nv=0;nv<4;nv++){
                float2 o=make_float2(Oacc[nv][2*r], Oacc[nv][2*r+1]);
                *(float2*)&dst[nv*8+tg*2]=o;
            }
        }
    }
}

// =================================================================
// Launch 4: combine ksplit halves + normalize + fp16 hi/lo split
// =================================================================
__global__ __launch_bounds__(256) void pack_ao_kernel(
    const float* __restrict__ aop, const float* __restrict__ lp,
    __half* __restrict__ oh, __half* __restrict__ ol)
{
    int i=blockIdx.x*256+threadIdx.x;
    if (i < BB*NQ*CC){
        int bq=i>>8, q=bq%NQ, b=bq/NQ, h=(i>>5)&7;
        size_t li=(size_t)(b*8+h)*NQ+q;
        float l=lp[li]+lp[(size_t)BB*HH*NQ+li];
        float v=(aop[i]+aop[(size_t)BB*NQ*CC+i])/l;
        __half hh=__float2half_rn(v);
        oh[i]=hh; ol[i]=__float2half_rn(v-__half2float(hh));
    }
}

// =================================================================
// Launch 5: output projection, 3-term hi/lo HMMA
// =================================================================
__global__ __launch_bounds__(256) void gemm_h3_kernel(
    const __half* __restrict__ Ah, const __half* __restrict__ Al,
    const uint2* __restrict__ Wfh, const uint2* __restrict__ Wfl,
    const float* __restrict__ bias, float* __restrict__ out, int M)
{
    const int tid=threadIdx.x, wid=tid>>5, lane=tid&31;
    const int g=lane>>2, tg=lane&3;
    const int wrow=wid>>1, wcol=wid&1;
    const int bm=blockIdx.y*64, bn=blockIdx.x*64;
    const int r0=bm+wrow*16+g, r1=r0+8;
    const int r0c=r0<M?r0:M-1, r1c=r1<M?r1:M-1;
    const int fbase=((bn>>3)+wcol*4)*512+lane;
    float c[4][4]={};
    #pragma unroll
    for (int ks=0;ks<16;ks++){
        const int k0=ks*16+tg*2;
        uint32_t ah[4], al[4];
        ah[0]=*(const uint32_t*)&Ah[r0c*256+k0];
        ah[1]=*(const uint32_t*)&Ah[r1c*256+k0];
        ah[2]=*(const uint32_t*)&Ah[r0c*256+k0+8];
        ah[3]=*(const uint32_t*)&Ah[r1c*256+k0+8];
        al[0]=*(const uint32_t*)&Al[r0c*256+k0];
        al[1]=*(const uint32_t*)&Al[r1c*256+k0];
        al[2]=*(const uint32_t*)&Al[r0c*256+k0+8];
        al[3]=*(const uint32_t*)&Al[r1c*256+k0+8];
        #pragma unroll
        for (int nt=0;nt<4;nt++){
            uint2 bh=Wfh[fbase+nt*512+ks*32];
            uint2 bl=Wfl[fbase+nt*512+ks*32];
            mma16816(c[nt], ah, bh);
            mma16816(c[nt], ah, bl);
            mma16816(c[nt], al, bh);
        }
    }
    const int cn=bn+wcol*32;
    #pragma unroll
    for (int nt=0;nt<4;nt++){
        int col=cn+nt*8+tg*2;
        float b0=bias[col], b1=bias[col+1];
        if (r0<M){ float2 o=make_float2(c[nt][0]+b0,c[nt][1]+b1); *(float2*)&out[r0*256+col]=o; }
        if (r1<M){ float2 o=make_float2(c[nt][2]+b0,c[nt][3]+b1); *(float2*)&out[r1*256+col]=o; }
    }
}

// ---------------- launch ----------------
extern "C" void kernel_launch(void* const* d_in, const int* in_sizes, int n_in,
                              void* d_out, int out_size)
{
    const float* query=(const float*)d_in[1];
    const float* ref  =(const float*)d_in[2];
    const float* kin  =(const float*)d_in[3];
    const float* vin  =(const float*)d_in[4];
    const unsigned char* mask=(const unsigned char*)d_in[6];
    const float* W1x=(const float*)d_in[7];
    const float* b1x=(const float*)d_in[8];
    const float* W2x=(const float*)d_in[9];
    const float* W1y=(const float*)d_in[10];
    const float* b1y=(const float*)d_in[11];
    const float* W2y=(const float*)d_in[12];
    const float* Wq =(const float*)d_in[13];
    const float* bq =(const float*)d_in[14];
    const float* Wk =(const float*)d_in[15];
    const float* bk =(const float*)d_in[16];
    const float* Wv =(const float*)d_in[17];
    const float* bv =(const float*)d_in[18];
    const float* Wp =(const float*)d_in[19];
    const float* bp =(const float*)d_in[20];
    float* out=(float*)d_out;

    void *pq,*pqa,*pka,*pva,*pkh,*pvh,*pwq,*pwk,*pwv,*pwph,*pwpl,*pw2h,*pw2l;
    void *pkf,*pvf,*pmb,*prx,*pry,*paop,*plp,*paoh,*paol;
    cudaGetSymbolAddress(&pq,  g_q);
    cudaGetSymbolAddress(&pqa, g_qah);
    cudaGetSymbolAddress(&pka, g_kah);
    cudaGetSymbolAddress(&pva, g_vah);
    cudaGetSymbolAddress(&pkh, g_kh);
    cudaGetSymbolAddress(&pvh, g_vh);
    cudaGetSymbolAddress(&pwq, g_wqf);
    cudaGetSymbolAddress(&pwk, g_wkf);
    cudaGetSymbolAddress(&pwv, g_wvf);
    cudaGetSymbolAddress(&pwph,g_wpfh);
    cudaGetSymbolAddress(&pwpl,g_wpfl);
    cudaGetSymbolAddress(&pw2h,g_w2fh);
    cudaGetSymbolAddress(&pw2l,g_w2fl);
    cudaGetSymbolAddress(&pkf, g_kf);
    cudaGetSymbolAddress(&pvf, g_vf);
    cudaGetSymbolAddress(&pmb, g_mb);
    cudaGetSymbolAddress(&prx, g_rx);
    cudaGetSymbolAddress(&pry, g_ry);
    cudaGetSymbolAddress(&paop,g_aop);
    cudaGetSymbolAddress(&plp, g_lp);
    cudaGetSymbolAddress(&paoh,g_aoh);
    cudaGetSymbolAddress(&paol,g_aol);

    const float qscale=(float)(0.17677669529663687 * 1.4426950408889634);
    const int MQ=BB*NQ;

    prep_kernel<<<9357,256>>>(query,kin,vin,Wq,Wk,Wv,Wp,W2x,W2y,mask,
        (__half*)pqa,(__half*)pka,(__half*)pva,
        (uint2*)pwq,(uint2*)pwk,(uint2*)pwv,(uint2*)pwph,(uint2*)pwpl,
        (uint2*)pw2h,(uint2*)pw2l,(unsigned*)pmb);
    gemm_all_kernel<<<dim3(4,128,3),256>>>((const __half*)pqa,(const __half*)pka,(const __half*)pva,
        (const uint2*)pwq,(const uint2*)pwk,(const uint2*)pwv,bq,bk,bv,
        (float*)pq,(__half*)pkh,(__half*)pvh,qscale);
    mid_kernel<<<5896,256>>>((const __half*)pkh,(const __half*)pvh,(uint2*)pkf,(uint2*)pvf,
        ref,W1x,b1x,W1y,b1y,(const uint2*)pw2h,(const uint2*)pw2l,(float*)prx,(float*)pry);
    attn_hmma_kernel<<<dim3(8,BB*HH,2),256>>>(
        (const float*)pq,(const uint2*)pkf,(const uint2*)pvf,
        (const float*)prx,(const float*)pry,(const unsigned*)pmb,(float*)paop,(float*)plp);
    pack_ao_kernel<<<(MQ*CC+255)/256,256>>>((const float*)paop,(const float*)plp,(__half*)paoh,(__half*)paol);
    gemm_h3_kernel<<<dim3(4,(MQ+63)/64),256>>>((const __half*)paoh,(const __half*)paol,
        (const uint2*)pwph,(const uint2*)pwpl,bp,out,MQ);
}

// round 8
// speedup vs baseline: 4.3106x; 1.0611x over previous
#include <cuda_runtime.h>
#include <cuda_fp16.h>
#include <cstdint>

#define BB 2
#define NQ 900
#define CC 256
#define HH 8
#define NN 4096
#define DH 32

// -------- scratch --------
__device__ float  g_q  [BB*NQ*CC];          // scaled Q projection (scale*log2e)
__device__ __half g_qah[BB*NQ*CC];
__device__ __half g_kah[BB*NN*CC];
__device__ __half g_vah[BB*NN*CC];
__device__ __half g_kh [BB*NN*CC];
__device__ __half g_vh [BB*NN*CC];
__device__ uint2  g_wqf[16384], g_wkf[16384], g_wvf[16384];
__device__ uint2  g_wpfh[16384], g_wpfl[16384];
__device__ uint2  g_w2fh[2048], g_w2fl[2048];
__device__ uint2  g_kf[BB*HH*512*2*32];
__device__ uint2  g_vf[BB*HH*256*4*32];
__device__ unsigned g_mb[BB*128];
__device__ float  g_rx[BB*HH*NQ*64];        // scaled by log2e
__device__ float  g_ry[BB*HH*NQ*64];        // scaled by log2e
__device__ float  g_aop[2*BB*NQ*CC];        // raw partial O (ksplit halves)
__device__ float  g_lp [2*BB*HH*NQ];        // partial l
__device__ __half g_aoh[BB*NQ*CC];
__device__ __half g_aol[BB*NQ*CC];

__device__ __forceinline__ uint32_t pack_h2(float lo, float hi){
    uint32_t r; asm("cvt.rn.f16x2.f32 %0, %1, %2;" : "=r"(r) : "f"(hi), "f"(lo)); return r;
}
__device__ __forceinline__ float lo_f(uint32_t x){ return __low2float(*(__half2*)&x); }
__device__ __forceinline__ float hi_f(uint32_t x){ return __high2float(*(__half2*)&x); }
__device__ __forceinline__ float ex2f(float x){ float r; asm("ex2.approx.f32 %0, %1;":"=f"(r):"f"(x)); return r; }
__device__ __forceinline__ void mma16816(float* c, const uint32_t* a, uint2 b){
    asm volatile("mma.sync.aligned.m16n8k16.row.col.f32.f16.f16.f32 "
      "{%0,%1,%2,%3}, {%4,%5,%6,%7}, {%8,%9}, {%0,%1,%2,%3};"
      : "+f"(c[0]),"+f"(c[1]),"+f"(c[2]),"+f"(c[3])
      : "r"(a[0]),"r"(a[1]),"r"(a[2]),"r"(a[3]),"r"(b.x),"r"(b.y));
}
__device__ __forceinline__ uint32_t smem_u32(const void* p){
    uint32_t a; asm("{ .reg .u64 t; cvta.to.shared.u64 t, %1; cvt.u32.u64 %0, t; }":"=r"(a):"l"(p)); return a;
}
__device__ __forceinline__ void cpa16(uint32_t dst, const void* src){
    asm volatile("cp.async.cg.shared.global [%0], [%1], 16;"::"r"(dst),"l"(src));
}
__device__ __forceinline__ void cpa_commit(){ asm volatile("cp.async.commit_group;":::"memory"); }
template<int N> __device__ __forceinline__ void cpa_wait(){ asm volatile("cp.async.wait_group %0;"::"n"(N):"memory"); }

#define L2E 1.4426950408889634f

// =================================================================
// Launch 0: mega prep (f2h x3, packW x4, packW2, mask)
// =================================================================
__global__ __launch_bounds__(256) void prep_kernel(
    const float* __restrict__ query, const float* __restrict__ kin, const float* __restrict__ vin,
    const float* __restrict__ Wq, const float* __restrict__ Wk, const float* __restrict__ Wv,
    const float* __restrict__ Wp, const float* __restrict__ W2x, const float* __restrict__ W2y,
    const unsigned char* __restrict__ mask,
    __half* __restrict__ qah, __half* __restrict__ kah, __half* __restrict__ vah,
    uint2* __restrict__ wqf, uint2* __restrict__ wkf, uint2* __restrict__ wvf,
    uint2* __restrict__ wpfh, uint2* __restrict__ wpfl,
    uint2* __restrict__ w2fh, uint2* __restrict__ w2fl, unsigned* __restrict__ mb)
{
    const int blk=blockIdx.x, tid=threadIdx.x;
    if (blk < 9092){
        const float* in; __half* out; int i;
        if (blk < 900){ in=query; out=qah; i=blk*256+tid; }
        else if (blk < 4996){ in=kin; out=kah; i=(blk-900)*256+tid; }
        else { in=vin; out=vah; i=(blk-4996)*256+tid; }
        float2 v=*(const float2*)&in[i*2];
        *(__half2*)&out[i*2]=__floats2half2_rn(v.x,v.y);
        return;
    }
    if (blk < 9348){
        const float* W; uint2 *fh, *fl=nullptr;
        int base;
        if (blk < 9156){ W=Wq; fh=wqf; base=9092; }
        else if (blk < 9220){ W=Wk; fh=wkf; base=9156; }
        else if (blk < 9284){ W=Wv; fh=wvf; base=9220; }
        else { W=Wp; fh=wpfh; fl=wpfl; base=9284; }
        int idx=(blk-base)*256+tid;
        int lane=idx&31, ks=(idx>>5)&15, n8=idx>>9;
        int k0=ks*16+(lane&3)*2, n=n8*8+(lane>>2);
        float w00=W[k0*256+n], w01=W[(k0+1)*256+n], w08=W[(k0+8)*256+n], w09=W[(k0+9)*256+n];
        uint2 hi=make_uint2(pack_h2(w00,w01), pack_h2(w08,w09));
        fh[idx]=hi;
        if (fl) fl[idx]=make_uint2(pack_h2(w00-lo_f(hi.x), w01-hi_f(hi.x)),
                                   pack_h2(w08-lo_f(hi.y), w09-hi_f(hi.y)));
        return;
    }
    if (blk < 9356){
        int idx=(blk-9348)*256+tid;
        int axis=idx>>10, r=idx&1023, lane=r&31, ks=r>>5;
        int j0=ks*16+(lane&3)*2, h=lane>>2;
        const float* W2=axis?W2y:W2x;
        float w00=W2[j0*8+h], w01=W2[(j0+1)*8+h], w08=W2[(j0+8)*8+h], w09=W2[(j0+9)*8+h];
        uint2 hi=make_uint2(pack_h2(w00,w01), pack_h2(w08,w09));
        w2fh[idx]=hi;
        w2fl[idx]=make_uint2(pack_h2(w00-lo_f(hi.x), w01-hi_f(hi.x)),
                             pack_h2(w08-lo_f(hi.y), w09-hi_f(hi.y)));
        return;
    }
    if (tid < BB*128){
        const unsigned char* p=mask+tid*32;
        unsigned v=0;
        #pragma unroll
        for (int i=0;i<32;i++) v |= (p[i]?1u:0u)<<i;
        mb[tid]=v;
    }
}

// =================================================================
// Launch 1: fused Q/K/V projection GEMM. grid (4, 128, 3)
// =================================================================
__global__ __launch_bounds__(256) void gemm_all_kernel(
    const __half* __restrict__ qa, const __half* __restrict__ ka, const __half* __restrict__ va,
    const uint2* __restrict__ wq, const uint2* __restrict__ wk, const uint2* __restrict__ wv,
    const float* __restrict__ bq, const float* __restrict__ bk, const float* __restrict__ bv,
    float* __restrict__ qout, __half* __restrict__ kh, __half* __restrict__ vh, float qscale)
{
    const int z=blockIdx.z;
    const __half* A; const uint2* Wf; const float* bias; int M;
    if (z==0){ A=qa; Wf=wq; bias=bq; M=BB*NQ; }
    else if (z==1){ A=ka; Wf=wk; bias=bk; M=BB*NN; }
    else { A=va; Wf=wv; bias=bv; M=BB*NN; }
    const int bm=blockIdx.y*64;
    if (bm >= M) return;
    const int tid=threadIdx.x, wid=tid>>5, lane=tid&31;
    const int g=lane>>2, tg=lane&3;
    const int wrow=wid>>1, wcol=wid&1;
    const int bn=blockIdx.x*64;
    const int r0=bm+wrow*16+g, r1=r0+8;
    const int r0c=r0<M?r0:M-1, r1c=r1<M?r1:M-1;
    const uint2* wf=Wf+((bn>>3)+wcol*4)*512+lane;
    float c[4][4]={};
    #pragma unroll
    for (int ks=0;ks<16;ks++){
        const int k0=ks*16+tg*2;
        uint32_t a[4];
        a[0]=*(const uint32_t*)&A[r0c*256+k0];
        a[1]=*(const uint32_t*)&A[r1c*256+k0];
        a[2]=*(const uint32_t*)&A[r0c*256+k0+8];
        a[3]=*(const uint32_t*)&A[r1c*256+k0+8];
        #pragma unroll
        for (int nt=0;nt<4;nt++) mma16816(c[nt], a, wf[nt*512+ks*32]);
    }
    const int cn=bn+wcol*32;
    #pragma unroll
    for (int nt=0;nt<4;nt++){
        int col=cn+nt*8+tg*2;
        float b0=bias[col], b1=bias[col+1];
        if (z==0){
            if (r0<M){ float2 o=make_float2((c[nt][0]+b0)*qscale,(c[nt][1]+b1)*qscale); *(float2*)&qout[r0*256+col]=o; }
            if (r1<M){ float2 o=make_float2((c[nt][2]+b0)*qscale,(c[nt][3]+b1)*qscale); *(float2*)&qout[r1*256+col]=o; }
        } else {
            __half* outh=(z==1)?kh:vh;
            if (r0<M) *(__half2*)&outh[r0*256+col]=__floats2half2_rn(c[nt][0]+b0,c[nt][1]+b1);
            if (r1<M) *(__half2*)&outh[r1*256+col]=__floats2half2_rn(c[nt][2]+b0,c[nt][3]+b1);
        }
    }
}

// =================================================================
// Launch 2: fused kf-pack [0,2048), vf-pack [2048,4096), rpe [4096,5896)
// =================================================================
__global__ __launch_bounds__(256) void mid_kernel(
    const __half* __restrict__ kh, const __half* __restrict__ vh,
    uint2* __restrict__ Kf, uint2* __restrict__ Vf,
    const float* __restrict__ ref,
    const float* __restrict__ W1x, const float* __restrict__ b1x,
    const float* __restrict__ W1y, const float* __restrict__ b1y,
    const uint2* __restrict__ w2fh, const uint2* __restrict__ w2fl,
    float* __restrict__ rx, float* __restrict__ ry)
{
    const int blk=blockIdx.x, tid=threadIdx.x;
    if (blk < 2048){
        int idx=blk*256+tid;
        int lane=idx&31, ds=(idx>>5)&1, kt8=(idx>>6)&511, bh=idx>>15;
        int b=bh>>3, h=bh&7;
        int key=kt8*8+(lane>>2), d0=ds*16+(lane&3)*2;
        const __half* src=kh+((size_t)b*NN+key)*CC+h*32+d0;
        Kf[idx]=make_uint2(*(const uint32_t*)src, *(const uint32_t*)(src+8));
        return;
    }
    if (blk < 4096){
        int idx=(blk-2048)*256+tid;
        int lane=idx&31, nt=(idx>>5)&3, kt16=(idx>>7)&255, bh=idx>>15;
        int b=bh>>3, h=bh&7;
        int key0=kt16*16+(lane&3)*2, d=nt*8+(lane>>2);
        const __half* src=vh+((size_t)b*NN+key0)*CC+h*32+d;
        __half2 x=__halves2half2(src[0],src[CC]);
        __half2 y=__halves2half2(src[8*CC],src[9*CC]);
        Vf[idx]=make_uint2(*(uint32_t*)&x, *(uint32_t*)&y);
        return;
    }
    // ---- RPE ----
    __shared__ float2 sAB[2][512];
    const int bq=blk-4096, b=bq/NQ, q=bq-b*NQ;
    float4 box=*(const float4*)&ref[bq*4];
    float lox=box.x-box.z*0.5f, hix=box.x+box.z*0.5f;
    float loy=box.y-box.w*0.5f, hiy=box.y+box.w*0.5f;
    for (int idx=tid; idx<1024; idx+=256){
        int axis=idx>>9, j=idx&511;
        const float* W1=axis?W1y:W1x;
        float u=W1[j], v=W1[512+j];
        float bb=(axis?b1y:b1x)[j];
        float LO=axis?loy:lox, HI=axis?hiy:hix;
        sAB[axis][j]=make_float2(fmaf(LO,u,fmaf(HI,v,bb)), u+v);
    }
    __syncthreads();
    const int wid=tid>>5, lane=tid&31, g=lane>>2, tg=lane&3;
    const int axis=wid>>2, mt=wid&3;
    const float p0=((float)(mt*16+g)+0.5f)*16.f;
    const float p1=p0+128.f;
    const uint2* fh=w2fh+axis*1024+lane;
    const uint2* fl=w2fl+axis*1024+lane;
    const float2* AB=sAB[axis];
    float c[4]={0.f,0.f,0.f,0.f};
    #pragma unroll 4
    for (int ks=0;ks<32;ks++){
        int j0=ks*16+tg*2;
        float2 ab0=AB[j0], ab1=AB[j0+1], ab8=AB[j0+8], ab9=AB[j0+9];
        float h00=fmaxf(fmaf(-p0,ab0.y,ab0.x),0.f);
        float h01=fmaxf(fmaf(-p0,ab1.y,ab1.x),0.f);
        float h10=fmaxf(fmaf(-p1,ab0.y,ab0.x),0.f);
        float h11=fmaxf(fmaf(-p1,ab1.y,ab1.x),0.f);
        float h08=fmaxf(fmaf(-p0,ab8.y,ab8.x),0.f);
        float h09=fmaxf(fmaf(-p0,ab9.y,ab9.x),0.f);
        float h18=fmaxf(fmaf(-p1,ab8.y,ab8.x),0.f);
        float h19=fmaxf(fmaf(-p1,ab9.y,ab9.x),0.f);
        uint32_t ah[4], al[4];
        ah[0]=pack_h2(h00,h01); ah[1]=pack_h2(h10,h11);
        ah[2]=pack_h2(h08,h09); ah[3]=pack_h2(h18,h19);
        al[0]=pack_h2(h00-lo_f(ah[0]), h01-hi_f(ah[0]));
        al[1]=pack_h2(h10-lo_f(ah[1]), h11-hi_f(ah[1]));
        al[2]=pack_h2(h08-lo_f(ah[2]), h09-hi_f(ah[2]));
        al[3]=pack_h2(h18-lo_f(ah[3]), h19-hi_f(ah[3]));
        uint2 bh=fh[ks*32], bl=fl[ks*32];
        mma16816(c, ah, bh);
        mma16816(c, ah, bl);
        mma16816(c, al, bh);
    }
    float* outp=axis?ry:rx;
    const int h2=tg*2, pos0=mt*16+g;
    size_t base0=((size_t)(b*8+h2)*NQ+q)*64;
    size_t base1=((size_t)(b*8+h2+1)*NQ+q)*64;
    outp[base0+pos0]    =c[0]*L2E;
    outp[base1+pos0]    =c[1]*L2E;
    outp[base0+pos0+8]  =c[2]*L2E;
    outp[base1+pos0+8]  =c[3]*L2E;
}

// =================================================================
// Launch 3 (PROFILED): HMMA flash attention, 2-way key split,
// cp.async double-buffered smem staging of Kf/Vf tiles.
// =================================================================
__global__ __launch_bounds__(256) void attn_hmma_kernel(
    const float* __restrict__ qp, const uint2* __restrict__ Kf, const uint2* __restrict__ Vf,
    const float* __restrict__ rxg, const float* __restrict__ ryg,
    const unsigned* __restrict__ mbits, float* __restrict__ aop, float* __restrict__ lp)
{
    __shared__ uint2 sbuf[2][2048];   // [buf][ kf 1024 | vf 1024 ] = 2 x 16KB
    const int tid=threadIdx.x, wid=tid>>5, lane=tid&31;
    const int g=lane>>2, tg=lane&3;
    const int bh=blockIdx.y, b=bh>>3, h=bh&7;
    const int z=blockIdx.z;
    const int q0=blockIdx.x*128 + wid*16;
    int qr[2]={q0+g, q0+g+8};
    int qc[2]={qr[0]<NQ?qr[0]:NQ-1, qr[1]<NQ?qr[1]:NQ-1};

    const uint2* KfB=Kf+(size_t)bh*32768;
    const uint2* VfB=Vf+(size_t)bh*32768;
    const uint32_t sb0=smem_u32(sbuf);

    // prologue prefetch: tile z*16 -> buf0
    {
        const char* ks_=(const char*)(KfB+(size_t)(z*16)*1024);
        const char* vs_=(const char*)(VfB+(size_t)(z*16)*1024);
        uint32_t d=sb0+tid*16;
        cpa16(d,        ks_+tid*16);
        cpa16(d+4096,   ks_+4096+tid*16);
        cpa16(d+8192,   vs_+tid*16);
        cpa16(d+12288,  vs_+4096+tid*16);
        cpa_commit();
    }

    uint32_t qf[2][4];
    #pragma unroll
    for (int ds=0;ds<2;ds++)
        #pragma unroll
        for (int r=0;r<2;r++){
            const float* p=qp+((size_t)b*NQ+qc[r])*CC+h*32+ds*16+tg*2;
            qf[ds][r]  =pack_h2(p[0],p[1]);
            qf[ds][r+2]=pack_h2(p[8],p[9]);
        }

    float rxv[2][16], shift[2];
    #pragma unroll
    for (int r=0;r<2;r++){
        const float* rp=rxg+((size_t)bh*NQ+qc[r])*64;
        float mx=-1e30f;
        #pragma unroll
        for (int j=0;j<8;j++){
            float2 v=*(const float2*)&rp[j*8+tg*2];
            rxv[r][j*2]=v.x; rxv[r][j*2+1]=v.y;
            mx=fmaxf(mx,fmaxf(v.x,v.y));
        }
        mx=fmaxf(mx,__shfl_xor_sync(0xffffffffu,mx,1));
        mx=fmaxf(mx,__shfl_xor_sync(0xffffffffu,mx,2));
        const float* yp=ryg+((size_t)bh*NQ+qc[r])*64;
        float my=-1e30f;
        #pragma unroll
        for (int j=0;j<16;j++) my=fmaxf(my,yp[tg+4*j]);
        my=fmaxf(my,__shfl_xor_sync(0xffffffffu,my,1));
        my=fmaxf(my,__shfl_xor_sync(0xffffffffu,my,2));
        shift[r]=mx+my;
    }

    const uint2 onesb = (lane<4)? make_uint2(0x3C003C00u,0x3C003C00u) : make_uint2(0u,0u);
    float Oacc[4][4];
    #pragma unroll
    for (int i=0;i<4;i++)
        #pragma unroll
        for (int j=0;j<4;j++) Oacc[i][j]=0.f;
    float ls[4]={0.f,0.f,0.f,0.f};

    for (int tt=0; tt<16; tt++){
        const int t=z*16+tt;
        __syncthreads();   // prev compute done everywhere before overwriting buf[(tt+1)&1]
        if (tt<15){
            const char* ks_=(const char*)(KfB+(size_t)(t+1)*1024);
            const char* vs_=(const char*)(VfB+(size_t)(t+1)*1024);
            uint32_t d=sb0+((tt+1)&1)*16384+tid*16;
            cpa16(d,        ks_+tid*16);
            cpa16(d+4096,   ks_+4096+tid*16);
            cpa16(d+8192,   vs_+tid*16);
            cpa16(d+12288,  vs_+4096+tid*16);
            cpa_commit();
            cpa_wait<1>();
        } else {
            cpa_wait<0>();
        }
        __syncthreads();   // staged tile visible to all

        const uint2* kbuf=sbuf[tt&1];
        const uint2* vbuf=kbuf+1024;

        float cp0[2][2], cp1[2][2];
        #pragma unroll
        for (int r=0;r<2;r++){
            const float* yp=ryg+((size_t)bh*NQ+qc[r])*64+2*t;
            cp0[r][0]=yp[0]-shift[r];
            cp0[r][1]=yp[1]-shift[r];
            cp1[r][0]=cp0[r][0]-144.26950408889634f;
            cp1[r][1]=cp0[r][1]-144.26950408889634f;
        }
        unsigned mbw[4];
        #pragma unroll
        for (int j=0;j<4;j++) mbw[j]=mbits[b*128+t*4+j];

        #pragma unroll
        for (int ks=0;ks<8;ks++){
            float sc[2][4];
            #pragma unroll
            for (int j=0;j<2;j++)
                #pragma unroll
                for (int i=0;i<4;i++) sc[j][i]=0.f;
            #pragma unroll
            for (int j=0;j<2;j++){
                const uint2* kf=kbuf+(2*ks+j)*64+lane;
                mma16816(sc[j], qf[0], kf[0]);
                mma16816(sc[j], qf[1], kf[32]);
            }
            float pv[2][4];
            const int yp=ks>>2;
            #pragma unroll
            for (int j=0;j<2;j++){
                const int nt=2*ks+j;
                #pragma unroll
                for (int i=0;i<4;i++){
                    const int row=i>>1, e=i&1;
                    bool mbit=(mbw[nt>>2]>>((nt&3)*8+tg*2+e))&1u;
                    float s=sc[j][i]+rxv[row][(nt&7)*2+e];
                    float cp=mbit?cp1[row][yp]:cp0[row][yp];
                    pv[j][i]=ex2f(s+cp);
                }
            }
            uint32_t pa[4];
            pa[0]=pack_h2(pv[0][0],pv[0][1]);
            pa[1]=pack_h2(pv[0][2],pv[0][3]);
            pa[2]=pack_h2(pv[1][0],pv[1][1]);
            pa[3]=pack_h2(pv[1][2],pv[1][3]);
            mma16816(ls, pa, onesb);
            const uint2* vf=vbuf+ks*128+lane;
            #pragma unroll
            for (int nv=0;nv<4;nv++)
                mma16816(Oacc[nv], pa, vf[nv*32]);
        }
    }

    if (tg==0){
        if (qr[0]<NQ) lp[(size_t)z*BB*HH*NQ + (size_t)bh*NQ + qr[0]] = ls[0];
        if (qr[1]<NQ) lp[(size_t)z*BB*HH*NQ + (size_t)bh*NQ + qr[1]] = ls[2];
    }
    #pragma unroll
    for (int r=0;r<2;r++){
        if (qr[r]<NQ){
            float* dst=aop + (size_t)z*BB*NQ*CC + ((size_t)b*NQ+qr[r])*CC + h*32;
            #pragma unroll
            for (int nv=0;nv<4;nv++){
                float2 o=make_float2(Oacc[nv][2*r], Oacc[nv][2*r+1]);
                *(float2*)&dst[nv*8+tg*2]=o;
            }
        }
    }
}

// =================================================================
// Launch 4: combine ksplit halves + normalize + fp16 hi/lo split
// =================================================================
__global__ __launch_bounds__(256) void pack_ao_kernel(
    const float* __restrict__ aop, const float* __restrict__ lp,
    __half* __restrict__ oh, __half* __restrict__ ol)
{
    int i=blockIdx.x*256+threadIdx.x;
    if (i < BB*NQ*CC){
        int bq=i>>8, q=bq%NQ, b=bq/NQ, h=(i>>5)&7;
        size_t li=(size_t)(b*8+h)*NQ+q;
        float l=lp[li]+lp[(size_t)BB*HH*NQ+li];
        float v=(aop[i]+aop[(size_t)BB*NQ*CC+i])/l;
        __half hh=__float2half_rn(v);
        oh[i]=hh; ol[i]=__float2half_rn(v-__half2float(hh));
    }
}

// =================================================================
// Launch 5: output projection, 3-term hi/lo HMMA
// =================================================================
__global__ __launch_bounds__(256) void gemm_h3_kernel(
    const __half* __restrict__ Ah, const __half* __restrict__ Al,
    const uint2* __restrict__ Wfh, const uint2* __restrict__ Wfl,
    const float* __restrict__ bias, float* __restrict__ out, int M)
{
    const int tid=threadIdx.x, wid=tid>>5, lane=tid&31;
    const int g=lane>>2, tg=lane&3;
    const int wrow=wid>>1, wcol=wid&1;
    const int bm=blockIdx.y*64, bn=blockIdx.x*64;
    const int r0=bm+wrow*16+g, r1=r0+8;
    const int r0c=r0<M?r0:M-1, r1c=r1<M?r1:M-1;
    const int fbase=((bn>>3)+wcol*4)*512+lane;
    float c[4][4]={};
    #pragma unroll
    for (int ks=0;ks<16;ks++){
        const int k0=ks*16+tg*2;
        uint32_t ah[4], al[4];
        ah[0]=*(const uint32_t*)&Ah[r0c*256+k0];
        ah[1]=*(const uint32_t*)&Ah[r1c*256+k0];
        ah[2]=*(const uint32_t*)&Ah[r0c*256+k0+8];
        ah[3]=*(const uint32_t*)&Ah[r1c*256+k0+8];
        al[0]=*(const uint32_t*)&Al[r0c*256+k0];
        al[1]=*(const uint32_t*)&Al[r1c*256+k0];
        al[2]=*(const uint32_t*)&Al[r0c*256+k0+8];
        al[3]=*(const uint32_t*)&Al[r1c*256+k0+8];
        #pragma unroll
        for (int nt=0;nt<4;nt++){
            uint2 bh=Wfh[fbase+nt*512+ks*32];
            uint2 bl=Wfl[fbase+nt*512+ks*32];
            mma16816(c[nt], ah, bh);
            mma16816(c[nt], ah, bl);
            mma16816(c[nt], al, bh);
        }
    }
    const int cn=bn+wcol*32;
    #pragma unroll
    for (int nt=0;nt<4;nt++){
        int col=cn+nt*8+tg*2;
        float b0=bias[col], b1=bias[col+1];
        if (r0<M){ float2 o=make_float2(c[nt][0]+b0,c[nt][1]+b1); *(float2*)&out[r0*256+col]=o; }
        if (r1<M){ float2 o=make_float2(c[nt][2]+b0,c[nt][3]+b1); *(float2*)&out[r1*256+col]=o; }
    }
}

// ---------------- launch ----------------
extern "C" void kernel_launch(void* const* d_in, const int* in_sizes, int n_in,
                              void* d_out, int out_size)
{
    const float* query=(const float*)d_in[1];
    const float* ref  =(const float*)d_in[2];
    const float* kin  =(const float*)d_in[3];
    const float* vin  =(const float*)d_in[4];
    const unsigned char* mask=(const unsigned char*)d_in[6];
    const float* W1x=(const float*)d_in[7];
    const float* b1x=(const float*)d_in[8];
    const float* W2x=(const float*)d_in[9];
    const float* W1y=(const float*)d_in[10];
    const float* b1y=(const float*)d_in[11];
    const float* W2y=(const float*)d_in[12];
    const float* Wq =(const float*)d_in[13];
    const float* bq =(const float*)d_in[14];
    const float* Wk =(const float*)d_in[15];
    const float* bk =(const float*)d_in[16];
    const float* Wv =(const float*)d_in[17];
    const float* bv =(const float*)d_in[18];
    const float* Wp =(const float*)d_in[19];
    const float* bp =(const float*)d_in[20];
    float* out=(float*)d_out;

    void *pq,*pqa,*pka,*pva,*pkh,*pvh,*pwq,*pwk,*pwv,*pwph,*pwpl,*pw2h,*pw2l;
    void *pkf,*pvf,*pmb,*prx,*pry,*paop,*plp,*paoh,*paol;
    cudaGetSymbolAddress(&pq,  g_q);
    cudaGetSymbolAddress(&pqa, g_qah);
    cudaGetSymbolAddress(&pka, g_kah);
    cudaGetSymbolAddress(&pva, g_vah);
    cudaGetSymbolAddress(&pkh, g_kh);
    cudaGetSymbolAddress(&pvh, g_vh);
    cudaGetSymbolAddress(&pwq, g_wqf);
    cudaGetSymbolAddress(&pwk, g_wkf);
    cudaGetSymbolAddress(&pwv, g_wvf);
    cudaGetSymbolAddress(&pwph,g_wpfh);
    cudaGetSymbolAddress(&pwpl,g_wpfl);
    cudaGetSymbolAddress(&pw2h,g_w2fh);
    cudaGetSymbolAddress(&pw2l,g_w2fl);
    cudaGetSymbolAddress(&pkf, g_kf);
    cudaGetSymbolAddress(&pvf, g_vf);
    cudaGetSymbolAddress(&pmb, g_mb);
    cudaGetSymbolAddress(&prx, g_rx);
    cudaGetSymbolAddress(&pry, g_ry);
    cudaGetSymbolAddress(&paop,g_aop);
    cudaGetSymbolAddress(&plp, g_lp);
    cudaGetSymbolAddress(&paoh,g_aoh);
    cudaGetSymbolAddress(&paol,g_aol);

    const float qscale=(float)(0.17677669529663687 * 1.4426950408889634);
    const int MQ=BB*NQ;

    prep_kernel<<<9357,256>>>(query,kin,vin,Wq,Wk,Wv,Wp,W2x,W2y,mask,
        (__half*)pqa,(__half*)pka,(__half*)pva,
        (uint2*)pwq,(uint2*)pwk,(uint2*)pwv,(uint2*)pwph,(uint2*)pwpl,
        (uint2*)pw2h,(uint2*)pw2l,(unsigned*)pmb);
    gemm_all_kernel<<<dim3(4,128,3),256>>>((const __half*)pqa,(const __half*)pka,(const __half*)pva,
        (const uint2*)pwq,(const uint2*)pwk,(const uint2*)pwv,bq,bk,bv,
        (float*)pq,(__half*)pkh,(__half*)pvh,qscale);
    mid_kernel<<<5896,256>>>((const __half*)pkh,(const __half*)pvh,(uint2*)pkf,(uint2*)pvf,
        ref,W1x,b1x,W1y,b1y,(const uint2*)pw2h,(const uint2*)pw2l,(float*)prx,(float*)pry);
    attn_hmma_kernel<<<dim3(8,BB*HH,2),256>>>(
        (const float*)pq,(const uint2*)pkf,(const uint2*)pvf,
        (const float*)prx,(const float*)pry,(const unsigned*)pmb,(float*)paop,(float*)plp);
    pack_ao_kernel<<<(MQ*CC+255)/256,256>>>((const float*)paop,(const float*)plp,(__half*)paoh,(__half*)paol);
    gemm_h3_kernel<<<dim3(4,(MQ+63)/64),256>>>((const __half*)paoh,(const __half*)paol,
        (const uint2*)pwph,(const uint2*)pwpl,bp,out,MQ);
}

// round 9
// speedup vs baseline: 4.4279x; 1.0272x over previous
#include <cuda_runtime.h>
#include <cuda_fp16.h>
#include <cstdint>

#define BB 2
#define NQ 900
#define CC 256
#define HH 8
#define NN 4096
#define DH 32
#define KSPLIT 4

// -------- scratch --------
__device__ float  g_q  [BB*NQ*CC];          // scaled Q projection (scale*log2e)
__device__ __half g_kh [BB*NN*CC];
__device__ __half g_vh [BB*NN*CC];
__device__ uint2  g_wqf[16384], g_wkf[16384], g_wvf[16384];
__device__ uint2  g_wpfh[16384], g_wpfl[16384];
__device__ uint2  g_w2fh[2048], g_w2fl[2048];
__device__ uint2  g_kf[BB*HH*512*2*32];
__device__ uint2  g_vf[BB*HH*256*4*32];
__device__ unsigned g_mb[BB*128];
__device__ float  g_rx[BB*HH*NQ*64];        // scaled by log2e
__device__ float  g_ry[BB*HH*NQ*64];        // scaled by log2e
__device__ float  g_aop[KSPLIT*BB*NQ*CC];   // raw partial O
__device__ float  g_lp [KSPLIT*BB*HH*NQ];   // partial l
__device__ __half g_aoh[BB*NQ*CC];
__device__ __half g_aol[BB*NQ*CC];

__device__ __forceinline__ uint32_t pack_h2(float lo, float hi){
    uint32_t r; asm("cvt.rn.f16x2.f32 %0, %1, %2;" : "=r"(r) : "f"(hi), "f"(lo)); return r;
}
__device__ __forceinline__ float lo_f(uint32_t x){ return __low2float(*(__half2*)&x); }
__device__ __forceinline__ float hi_f(uint32_t x){ return __high2float(*(__half2*)&x); }
__device__ __forceinline__ float ex2f(float x){ float r; asm("ex2.approx.f32 %0, %1;":"=f"(r):"f"(x)); return r; }
__device__ __forceinline__ void mma16816(float* c, const uint32_t* a, uint2 b){
    asm volatile("mma.sync.aligned.m16n8k16.row.col.f32.f16.f16.f32 "
      "{%0,%1,%2,%3}, {%4,%5,%6,%7}, {%8,%9}, {%0,%1,%2,%3};"
      : "+f"(c[0]),"+f"(c[1]),"+f"(c[2]),"+f"(c[3])
      : "r"(a[0]),"r"(a[1]),"r"(a[2]),"r"(a[3]),"r"(b.x),"r"(b.y));
}
__device__ __forceinline__ uint32_t smem_u32(const void* p){
    uint32_t a; asm("{ .reg .u64 t; cvta.to.shared.u64 t, %1; cvt.u32.u64 %0, t; }":"=r"(a):"l"(p)); return a;
}
__device__ __forceinline__ void cpa16(uint32_t dst, const void* src){
    asm volatile("cp.async.cg.shared.global [%0], [%1], 16;"::"r"(dst),"l"(src));
}
__device__ __forceinline__ void cpa_commit(){ asm volatile("cp.async.commit_group;":::"memory"); }
template<int N> __device__ __forceinline__ void cpa_wait(){ asm volatile("cp.async.wait_group %0;"::"n"(N):"memory"); }

#define L2E 1.4426950408889634f

// =================================================================
// Launch 0: prep (packW x4 [0,256), packW2 [256,264), mask [264])
// =================================================================
__global__ __launch_bounds__(256) void prep_kernel(
    const float* __restrict__ Wq, const float* __restrict__ Wk, const float* __restrict__ Wv,
    const float* __restrict__ Wp, const float* __restrict__ W2x, const float* __restrict__ W2y,
    const unsigned char* __restrict__ mask,
    uint2* __restrict__ wqf, uint2* __restrict__ wkf, uint2* __restrict__ wvf,
    uint2* __restrict__ wpfh, uint2* __restrict__ wpfl,
    uint2* __restrict__ w2fh, uint2* __restrict__ w2fl, unsigned* __restrict__ mb)
{
    const int blk=blockIdx.x, tid=threadIdx.x;
    if (blk < 256){
        const float* W; uint2 *fh, *fl=nullptr;
        int base;
        if (blk < 64){ W=Wq; fh=wqf; base=0; }
        else if (blk < 128){ W=Wk; fh=wkf; base=64; }
        else if (blk < 192){ W=Wv; fh=wvf; base=128; }
        else { W=Wp; fh=wpfh; fl=wpfl; base=192; }
        int idx=(blk-base)*256+tid;
        int lane=idx&31, ks=(idx>>5)&15, n8=idx>>9;
        int k0=ks*16+(lane&3)*2, n=n8*8+(lane>>2);
        float w00=W[k0*256+n], w01=W[(k0+1)*256+n], w08=W[(k0+8)*256+n], w09=W[(k0+9)*256+n];
        uint2 hi=make_uint2(pack_h2(w00,w01), pack_h2(w08,w09));
        fh[idx]=hi;
        if (fl) fl[idx]=make_uint2(pack_h2(w00-lo_f(hi.x), w01-hi_f(hi.x)),
                                   pack_h2(w08-lo_f(hi.y), w09-hi_f(hi.y)));
        return;
    }
    if (blk < 264){
        int idx=(blk-256)*256+tid;
        int axis=idx>>10, r=idx&1023, lane=r&31, ks=r>>5;
        int j0=ks*16+(lane&3)*2, h=lane>>2;
        const float* W2=axis?W2y:W2x;
        float w00=W2[j0*8+h], w01=W2[(j0+1)*8+h], w08=W2[(j0+8)*8+h], w09=W2[(j0+9)*8+h];
        uint2 hi=make_uint2(pack_h2(w00,w01), pack_h2(w08,w09));
        w2fh[idx]=hi;
        w2fl[idx]=make_uint2(pack_h2(w00-lo_f(hi.x), w01-hi_f(hi.x)),
                             pack_h2(w08-lo_f(hi.y), w09-hi_f(hi.y)));
        return;
    }
    if (tid < BB*128){
        const unsigned char* p=mask+tid*32;
        unsigned v=0;
        #pragma unroll
        for (int i=0;i<32;i++) v |= (p[i]?1u:0u)<<i;
        mb[tid]=v;
    }
}

// =================================================================
// Launch 1: fused Q/K/V projection GEMM, fp32 A in-register fp16 pack.
// grid (4, 128, 3)
// =================================================================
__global__ __launch_bounds__(256) void gemm_all_kernel(
    const float* __restrict__ qa, const float* __restrict__ ka, const float* __restrict__ va,
    const uint2* __restrict__ wq, const uint2* __restrict__ wk, const uint2* __restrict__ wv,
    const float* __restrict__ bq, const float* __restrict__ bk, const float* __restrict__ bv,
    float* __restrict__ qout, __half* __restrict__ kh, __half* __restrict__ vh, float qscale)
{
    const int z=blockIdx.z;
    const float* A; const uint2* Wf; const float* bias; int M;
    if (z==0){ A=qa; Wf=wq; bias=bq; M=BB*NQ; }
    else if (z==1){ A=ka; Wf=wk; bias=bk; M=BB*NN; }
    else { A=va; Wf=wv; bias=bv; M=BB*NN; }
    const int bm=blockIdx.y*64;
    if (bm >= M) return;
    const int tid=threadIdx.x, wid=tid>>5, lane=tid&31;
    const int g=lane>>2, tg=lane&3;
    const int wrow=wid>>1, wcol=wid&1;
    const int bn=blockIdx.x*64;
    const int r0=bm+wrow*16+g, r1=r0+8;
    const int r0c=r0<M?r0:M-1, r1c=r1<M?r1:M-1;
    const uint2* wf=Wf+((bn>>3)+wcol*4)*512+lane;
    float c[4][4]={};
    #pragma unroll
    for (int ks=0;ks<16;ks++){
        const int k0=ks*16+tg*2;
        float2 v0=*(const float2*)&A[r0c*256+k0];
        float2 v1=*(const float2*)&A[r1c*256+k0];
        float2 v2=*(const float2*)&A[r0c*256+k0+8];
        float2 v3=*(const float2*)&A[r1c*256+k0+8];
        uint32_t a[4];
        a[0]=pack_h2(v0.x,v0.y);
        a[1]=pack_h2(v1.x,v1.y);
        a[2]=pack_h2(v2.x,v2.y);
        a[3]=pack_h2(v3.x,v3.y);
        #pragma unroll
        for (int nt=0;nt<4;nt++) mma16816(c[nt], a, wf[nt*512+ks*32]);
    }
    const int cn=bn+wcol*32;
    #pragma unroll
    for (int nt=0;nt<4;nt++){
        int col=cn+nt*8+tg*2;
        float b0=bias[col], b1=bias[col+1];
        if (z==0){
            if (r0<M){ float2 o=make_float2((c[nt][0]+b0)*qscale,(c[nt][1]+b1)*qscale); *(float2*)&qout[r0*256+col]=o; }
            if (r1<M){ float2 o=make_float2((c[nt][2]+b0)*qscale,(c[nt][3]+b1)*qscale); *(float2*)&qout[r1*256+col]=o; }
        } else {
            __half* outh=(z==1)?kh:vh;
            if (r0<M) *(__half2*)&outh[r0*256+col]=__floats2half2_rn(c[nt][0]+b0,c[nt][1]+b1);
            if (r1<M) *(__half2*)&outh[r1*256+col]=__floats2half2_rn(c[nt][2]+b0,c[nt][3]+b1);
        }
    }
}

// =================================================================
// Launch 2: fused kf-pack [0,2048), vf-pack [2048,4096), rpe [4096,5896)
// =================================================================
__global__ __launch_bounds__(256) void mid_kernel(
    const __half* __restrict__ kh, const __half* __restrict__ vh,
    uint2* __restrict__ Kf, uint2* __restrict__ Vf,
    const float* __restrict__ ref,
    const float* __restrict__ W1x, const float* __restrict__ b1x,
    const float* __restrict__ W1y, const float* __restrict__ b1y,
    const uint2* __restrict__ w2fh, const uint2* __restrict__ w2fl,
    float* __restrict__ rx, float* __restrict__ ry)
{
    const int blk=blockIdx.x, tid=threadIdx.x;
    if (blk < 2048){
        int idx=blk*256+tid;
        int lane=idx&31, ds=(idx>>5)&1, kt8=(idx>>6)&511, bh=idx>>15;
        int b=bh>>3, h=bh&7;
        int key=kt8*8+(lane>>2), d0=ds*16+(lane&3)*2;
        const __half* src=kh+((size_t)b*NN+key)*CC+h*32+d0;
        Kf[idx]=make_uint2(*(const uint32_t*)src, *(const uint32_t*)(src+8));
        return;
    }
    if (blk < 4096){
        int idx=(blk-2048)*256+tid;
        int lane=idx&31, nt=(idx>>5)&3, kt16=(idx>>7)&255, bh=idx>>15;
        int b=bh>>3, h=bh&7;
        int key0=kt16*16+(lane&3)*2, d=nt*8+(lane>>2);
        const __half* src=vh+((size_t)b*NN+key0)*CC+h*32+d;
        __half2 x=__halves2half2(src[0],src[CC]);
        __half2 y=__halves2half2(src[8*CC],src[9*CC]);
        Vf[idx]=make_uint2(*(uint32_t*)&x, *(uint32_t*)&y);
        return;
    }
    // ---- RPE ----
    __shared__ float2 sAB[2][512];
    const int bq=blk-4096, b=bq/NQ, q=bq-b*NQ;
    float4 box=*(const float4*)&ref[bq*4];
    float lox=box.x-box.z*0.5f, hix=box.x+box.z*0.5f;
    float loy=box.y-box.w*0.5f, hiy=box.y+box.w*0.5f;
    for (int idx=tid; idx<1024; idx+=256){
        int axis=idx>>9, j=idx&511;
        const float* W1=axis?W1y:W1x;
        float u=W1[j], v=W1[512+j];
        float bb=(axis?b1y:b1x)[j];
        float LO=axis?loy:lox, HI=axis?hiy:hix;
        sAB[axis][j]=make_float2(fmaf(LO,u,fmaf(HI,v,bb)), u+v);
    }
    __syncthreads();
    const int wid=tid>>5, lane=tid&31, g=lane>>2, tg=lane&3;
    const int axis=wid>>2, mt=wid&3;
    const float p0=((float)(mt*16+g)+0.5f)*16.f;
    const float p1=p0+128.f;
    const uint2* fh=w2fh+axis*1024+lane;
    const uint2* fl=w2fl+axis*1024+lane;
    const float2* AB=sAB[axis];
    float c[4]={0.f,0.f,0.f,0.f};
    #pragma unroll 4
    for (int ks=0;ks<32;ks++){
        int j0=ks*16+tg*2;
        float2 ab0=AB[j0], ab1=AB[j0+1], ab8=AB[j0+8], ab9=AB[j0+9];
        float h00=fmaxf(fmaf(-p0,ab0.y,ab0.x),0.f);
        float h01=fmaxf(fmaf(-p0,ab1.y,ab1.x),0.f);
        float h10=fmaxf(fmaf(-p1,ab0.y,ab0.x),0.f);
        float h11=fmaxf(fmaf(-p1,ab1.y,ab1.x),0.f);
        float h08=fmaxf(fmaf(-p0,ab8.y,ab8.x),0.f);
        float h09=fmaxf(fmaf(-p0,ab9.y,ab9.x),0.f);
        float h18=fmaxf(fmaf(-p1,ab8.y,ab8.x),0.f);
        float h19=fmaxf(fmaf(-p1,ab9.y,ab9.x),0.f);
        uint32_t ah[4], al[4];
        ah[0]=pack_h2(h00,h01); ah[1]=pack_h2(h10,h11);
        ah[2]=pack_h2(h08,h09); ah[3]=pack_h2(h18,h19);
        al[0]=pack_h2(h00-lo_f(ah[0]), h01-hi_f(ah[0]));
        al[1]=pack_h2(h10-lo_f(ah[1]), h11-hi_f(ah[1]));
        al[2]=pack_h2(h08-lo_f(ah[2]), h09-hi_f(ah[2]));
        al[3]=pack_h2(h18-lo_f(ah[3]), h19-hi_f(ah[3]));
        uint2 bh=fh[ks*32], bl=fl[ks*32];
        mma16816(c, ah, bh);
        mma16816(c, ah, bl);
        mma16816(c, al, bh);
    }
    float* outp=axis?ry:rx;
    const int h2=tg*2, pos0=mt*16+g;
    size_t base0=((size_t)(b*8+h2)*NQ+q)*64;
    size_t base1=((size_t)(b*8+h2+1)*NQ+q)*64;
    outp[base0+pos0]    =c[0]*L2E;
    outp[base1+pos0]    =c[1]*L2E;
    outp[base0+pos0+8]  =c[2]*L2E;
    outp[base1+pos0+8]  =c[3]*L2E;
}

// =================================================================
// Launch 3 (PROFILED): HMMA flash attention, 4-way key split,
// cp.async double-buffered smem staging.  grid (8, 16, 4)
// =================================================================
__global__ __launch_bounds__(256) void attn_hmma_kernel(
    const float* __restrict__ qp, const uint2* __restrict__ Kf, const uint2* __restrict__ Vf,
    const float* __restrict__ rxg, const float* __restrict__ ryg,
    const unsigned* __restrict__ mbits, float* __restrict__ aop, float* __restrict__ lp)
{
    __shared__ uint2 sbuf[2][2048];   // [buf][ kf 1024 | vf 1024 ] = 2 x 16KB
    const int tid=threadIdx.x, wid=tid>>5, lane=tid&31;
    const int g=lane>>2, tg=lane&3;
    const int bh=blockIdx.y, b=bh>>3, h=bh&7;
    const int z=blockIdx.z;
    const int q0=blockIdx.x*128 + wid*16;
    int qr[2]={q0+g, q0+g+8};
    int qc[2]={qr[0]<NQ?qr[0]:NQ-1, qr[1]<NQ?qr[1]:NQ-1};

    const uint2* KfB=Kf+(size_t)bh*32768;
    const uint2* VfB=Vf+(size_t)bh*32768;
    const uint32_t sb0=smem_u32(sbuf);

    // prologue prefetch: tile z*8 -> buf0
    {
        const char* ks_=(const char*)(KfB+(size_t)(z*8)*1024);
        const char* vs_=(const char*)(VfB+(size_t)(z*8)*1024);
        uint32_t d=sb0+tid*16;
        cpa16(d,        ks_+tid*16);
        cpa16(d+4096,   ks_+4096+tid*16);
        cpa16(d+8192,   vs_+tid*16);
        cpa16(d+12288,  vs_+4096+tid*16);
        cpa_commit();
    }

    uint32_t qf[2][4];
    #pragma unroll
    for (int ds=0;ds<2;ds++)
        #pragma unroll
        for (int r=0;r<2;r++){
            const float* p=qp+((size_t)b*NQ+qc[r])*CC+h*32+ds*16+tg*2;
            qf[ds][r]  =pack_h2(p[0],p[1]);
            qf[ds][r+2]=pack_h2(p[8],p[9]);
        }

    float rxv[2][16], shift[2];
    #pragma unroll
    for (int r=0;r<2;r++){
        const float* rp=rxg+((size_t)bh*NQ+qc[r])*64;
        float mx=-1e30f;
        #pragma unroll
        for (int j=0;j<8;j++){
            float2 v=*(const float2*)&rp[j*8+tg*2];
            rxv[r][j*2]=v.x; rxv[r][j*2+1]=v.y;
            mx=fmaxf(mx,fmaxf(v.x,v.y));
        }
        mx=fmaxf(mx,__shfl_xor_sync(0xffffffffu,mx,1));
        mx=fmaxf(mx,__shfl_xor_sync(0xffffffffu,mx,2));
        const float* yp=ryg+((size_t)bh*NQ+qc[r])*64;
        float my=-1e30f;
        #pragma unroll
        for (int j=0;j<16;j++) my=fmaxf(my,yp[tg+4*j]);
        my=fmaxf(my,__shfl_xor_sync(0xffffffffu,my,1));
        my=fmaxf(my,__shfl_xor_sync(0xffffffffu,my,2));
        shift[r]=mx+my;
    }

    const uint2 onesb = (lane<4)? make_uint2(0x3C003C00u,0x3C003C00u) : make_uint2(0u,0u);
    float Oacc[4][4];
    #pragma unroll
    for (int i=0;i<4;i++)
        #pragma unroll
        for (int j=0;j<4;j++) Oacc[i][j]=0.f;
    float ls[4]={0.f,0.f,0.f,0.f};

    for (int tt=0; tt<8; tt++){
        const int t=z*8+tt;
        __syncthreads();
        if (tt<7){
            const char* ks_=(const char*)(KfB+(size_t)(t+1)*1024);
            const char* vs_=(const char*)(VfB+(size_t)(t+1)*1024);
            uint32_t d=sb0+((tt+1)&1)*16384+tid*16;
            cpa16(d,        ks_+tid*16);
            cpa16(d+4096,   ks_+4096+tid*16);
            cpa16(d+8192,   vs_+tid*16);
            cpa16(d+12288,  vs_+4096+tid*16);
            cpa_commit();
            cpa_wait<1>();
        } else {
            cpa_wait<0>();
        }
        __syncthreads();

        const uint2* kbuf=sbuf[tt&1];
        const uint2* vbuf=kbuf+1024;

        float cp0[2][2], cp1[2][2];
        #pragma unroll
        for (int r=0;r<2;r++){
            const float* yp=ryg+((size_t)bh*NQ+qc[r])*64+2*t;
            cp0[r][0]=yp[0]-shift[r];
            cp0[r][1]=yp[1]-shift[r];
            cp1[r][0]=cp0[r][0]-144.26950408889634f;
            cp1[r][1]=cp0[r][1]-144.26950408889634f;
        }
        unsigned mbw[4];
        #pragma unroll
        for (int j=0;j<4;j++) mbw[j]=mbits[b*128+t*4+j];

        #pragma unroll
        for (int ks=0;ks<8;ks++){
            float sc[2][4];
            #pragma unroll
            for (int j=0;j<2;j++)
                #pragma unroll
                for (int i=0;i<4;i++) sc[j][i]=0.f;
            #pragma unroll
            for (int j=0;j<2;j++){
                const uint2* kf=kbuf+(2*ks+j)*64+lane;
                mma16816(sc[j], qf[0], kf[0]);
                mma16816(sc[j], qf[1], kf[32]);
            }
            float pv[2][4];
            const int yp=ks>>2;
            #pragma unroll
            for (int j=0;j<2;j++){
                const int nt=2*ks+j;
                #pragma unroll
                for (int i=0;i<4;i++){
                    const int row=i>>1, e=i&1;
                    bool mbit=(mbw[nt>>2]>>((nt&3)*8+tg*2+e))&1u;
                    float s=sc[j][i]+rxv[row][(nt&7)*2+e];
                    float cp=mbit?cp1[row][yp]:cp0[row][yp];
                    pv[j][i]=ex2f(s+cp);
                }
            }
            uint32_t pa[4];
            pa[0]=pack_h2(pv[0][0],pv[0][1]);
            pa[1]=pack_h2(pv[0][2],pv[0][3]);
            pa[2]=pack_h2(pv[1][0],pv[1][1]);
            pa[3]=pack_h2(pv[1][2],pv[1][3]);
            mma16816(ls, pa, onesb);
            const uint2* vf=vbuf+ks*128+lane;
            #pragma unroll
            for (int nv=0;nv<4;nv++)
                mma16816(Oacc[nv], pa, vf[nv*32]);
        }
    }

    if (tg==0){
        if (qr[0]<NQ) lp[(size_t)z*BB*HH*NQ + (size_t)bh*NQ + qr[0]] = ls[0];
        if (qr[1]<NQ) lp[(size_t)z*BB*HH*NQ + (size_t)bh*NQ + qr[1]] = ls[2];
    }
    #pragma unroll
    for (int r=0;r<2;r++){
        if (qr[r]<NQ){
            float* dst=aop + (size_t)z*BB*NQ*CC + ((size_t)b*NQ+qr[r])*CC + h*32;
            #pragma unroll
            for (int nv=0;nv<4;nv++){
                float2 o=make_float2(Oacc[nv][2*r], Oacc[nv][2*r+1]);
                *(float2*)&dst[nv*8+tg*2]=o;
            }
        }
    }
}

// =================================================================
// Launch 4: combine 4 ksplit partials + normalize + fp16 hi/lo split
// =================================================================
__global__ __launch_bounds__(256) void pack_ao_kernel(
    const float* __restrict__ aop, const float* __restrict__ lp,
    __half* __restrict__ oh, __half* __restrict__ ol)
{
    int i=blockIdx.x*256+threadIdx.x;
    if (i < BB*NQ*CC){
        int bq=i>>8, q=bq%NQ, b=bq/NQ, h=(i>>5)&7;
        size_t li=(size_t)(b*8+h)*NQ+q;
        float l=0.f, v=0.f;
        #pragma unroll
        for (int zz=0;zz<KSPLIT;zz++){
            l+=lp[(size_t)zz*BB*HH*NQ+li];
            v+=aop[(size_t)zz*BB*NQ*CC+i];
        }
        v/=l;
        __half hh=__float2half_rn(v);
        oh[i]=hh; ol[i]=__float2half_rn(v-__half2float(hh));
    }
}

// =================================================================
// Launch 5: output projection, 3-term hi/lo HMMA
// =================================================================
__global__ __launch_bounds__(256) void gemm_h3_kernel(
    const __half* __restrict__ Ah, const __half* __restrict__ Al,
    const uint2* __restrict__ Wfh, const uint2* __restrict__ Wfl,
    const float* __restrict__ bias, float* __restrict__ out, int M)
{
    const int tid=threadIdx.x, wid=tid>>5, lane=tid&31;
    const int g=lane>>2, tg=lane&3;
    const int wrow=wid>>1, wcol=wid&1;
    const int bm=blockIdx.y*64, bn=blockIdx.x*64;
    const int r0=bm+wrow*16+g, r1=r0+8;
    const int r0c=r0<M?r0:M-1, r1c=r1<M?r1:M-1;
    const int fbase=((bn>>3)+wcol*4)*512+lane;
    float c[4][4]={};
    #pragma unroll
    for (int ks=0;ks<16;ks++){
        const int k0=ks*16+tg*2;
        uint32_t ah[4], al[4];
        ah[0]=*(const uint32_t*)&Ah[r0c*256+k0];
        ah[1]=*(const uint32_t*)&Ah[r1c*256+k0];
        ah[2]=*(const uint32_t*)&Ah[r0c*256+k0+8];
        ah[3]=*(const uint32_t*)&Ah[r1c*256+k0+8];
        al[0]=*(const uint32_t*)&Al[r0c*256+k0];
        al[1]=*(const uint32_t*)&Al[r1c*256+k0];
        al[2]=*(const uint32_t*)&Al[r0c*256+k0+8];
        al[3]=*(const uint32_t*)&Al[r1c*256+k0+8];
        #pragma unroll
        for (int nt=0;nt<4;nt++){
            uint2 bh=Wfh[fbase+nt*512+ks*32];
            uint2 bl=Wfl[fbase+nt*512+ks*32];
            mma16816(c[nt], ah, bh);
            mma16816(c[nt], ah, bl);
            mma16816(c[nt], al, bh);
        }
    }
    const int cn=bn+wcol*32;
    #pragma unroll
    for (int nt=0;nt<4;nt++){
        int col=cn+nt*8+tg*2;
        float b0=bias[col], b1=bias[col+1];
        if (r0<M){ float2 o=make_float2(c[nt][0]+b0,c[nt][1]+b1); *(float2*)&out[r0*256+col]=o; }
        if (r1<M){ float2 o=make_float2(c[nt][2]+b0,c[nt][3]+b1); *(float2*)&out[r1*256+col]=o; }
    }
}

// ---------------- launch ----------------
extern "C" void kernel_launch(void* const* d_in, const int* in_sizes, int n_in,
                              void* d_out, int out_size)
{
    const float* query=(const float*)d_in[1];
    const float* ref  =(const float*)d_in[2];
    const float* kin  =(const float*)d_in[3];
    const float* vin  =(const float*)d_in[4];
    const unsigned char* mask=(const unsigned char*)d_in[6];
    const float* W1x=(const float*)d_in[7];
    const float* b1x=(const float*)d_in[8];
    const float* W2x=(const float*)d_in[9];
    const float* W1y=(const float*)d_in[10];
    const float* b1y=(const float*)d_in[11];
    const float* W2y=(const float*)d_in[12];
    const float* Wq =(const float*)d_in[13];
    const float* bq =(const float*)d_in[14];
    const float* Wk =(const float*)d_in[15];
    const float* bk =(const float*)d_in[16];
    const float* Wv =(const float*)d_in[17];
    const float* bv =(const float*)d_in[18];
    const float* Wp =(const float*)d_in[19];
    const float* bp =(const float*)d_in[20];
    float* out=(float*)d_out;

    void *pq,*pkh,*pvh,*pwq,*pwk,*pwv,*pwph,*pwpl,*pw2h,*pw2l;
    void *pkf,*pvf,*pmb,*prx,*pry,*paop,*plp,*paoh,*paol;
    cudaGetSymbolAddress(&pq,  g_q);
    cudaGetSymbolAddress(&pkh, g_kh);
    cudaGetSymbolAddress(&pvh, g_vh);
    cudaGetSymbolAddress(&pwq, g_wqf);
    cudaGetSymbolAddress(&pwk, g_wkf);
    cudaGetSymbolAddress(&pwv, g_wvf);
    cudaGetSymbolAddress(&pwph,g_wpfh);
    cudaGetSymbolAddress(&pwpl,g_wpfl);
    cudaGetSymbolAddress(&pw2h,g_w2fh);
    cudaGetSymbolAddress(&pw2l,g_w2fl);
    cudaGetSymbolAddress(&pkf, g_kf);
    cudaGetSymbolAddress(&pvf, g_vf);
    cudaGetSymbolAddress(&pmb, g_mb);
    cudaGetSymbolAddress(&prx, g_rx);
    cudaGetSymbolAddress(&pry, g_ry);
    cudaGetSymbolAddress(&paop,g_aop);
    cudaGetSymbolAddress(&plp, g_lp);
    cudaGetSymbolAddress(&paoh,g_aoh);
    cudaGetSymbolAddress(&paol,g_aol);

    const float qscale=(float)(0.17677669529663687 * 1.4426950408889634);
    const int MQ=BB*NQ;

    prep_kernel<<<265,256>>>(Wq,Wk,Wv,Wp,W2x,W2y,mask,
        (uint2*)pwq,(uint2*)pwk,(uint2*)pwv,(uint2*)pwph,(uint2*)pwpl,
        (uint2*)pw2h,(uint2*)pw2l,(unsigned*)pmb);
    gemm_all_kernel<<<dim3(4,128,3),256>>>(query,kin,vin,
        (const uint2*)pwq,(const uint2*)pwk,(const uint2*)pwv,bq,bk,bv,
        (float*)pq,(__half*)pkh,(__half*)pvh,qscale);
    mid_kernel<<<5896,256>>>((const __half*)pkh,(const __half*)pvh,(uint2*)pkf,(uint2*)pvf,
        ref,W1x,b1x,W1y,b1y,(const uint2*)pw2h,(const uint2*)pw2l,(float*)prx,(float*)pry);
    attn_hmma_kernel<<<dim3(8,BB*HH,KSPLIT),256>>>(
        (const float*)pq,(const uint2*)pkf,(const uint2*)pvf,
        (const float*)prx,(const float*)pry,(const unsigned*)pmb,(float*)paop,(float*)plp);
    pack_ao_kernel<<<(MQ*CC+255)/256,256>>>((const float*)paop,(const float*)plp,(__half*)paoh,(__half*)paol);
    gemm_h3_kernel<<<dim3(4,(MQ+63)/64),256>>>((const __half*)paoh,(const __half*)paol,
        (const uint2*)pwph,(const uint2*)pwpl,bp,out,MQ);
}

// round 10
// speedup vs baseline: 4.7245x; 1.0670x over previous
#include <cuda_runtime.h>
#include <cuda_fp16.h>
#include <cstdint>

#define BB 2
#define NQ 900
#define CC 256
#define HH 8
#define NN 4096
#define DH 32
#define KSPLIT 2

// -------- scratch --------
__device__ float  g_q  [BB*NQ*CC];          // scaled Q projection (scale*log2e)
__device__ uint2  g_wqf[16384], g_wkf[16384], g_wvf[16384];
__device__ uint2  g_wpfh[16384], g_wpfl[16384];
__device__ uint2  g_w2fh[2048], g_w2fl[2048];
__device__ uint2  g_kf[BB*HH*512*2*32];
__device__ uint2  g_vf[BB*HH*256*4*32];
__device__ unsigned g_mb[BB*128];
__device__ float  g_rx[BB*HH*NQ*64];        // scaled by log2e
__device__ float  g_ry[BB*HH*NQ*64];        // scaled by log2e
__device__ float  g_aop[KSPLIT*BB*NQ*CC];   // raw partial O
__device__ float  g_lp [KSPLIT*BB*HH*NQ];   // partial l
__device__ __half g_aoh[BB*NQ*CC];
__device__ __half g_aol[BB*NQ*CC];

__device__ __forceinline__ uint32_t pack_h2(float lo, float hi){
    uint32_t r; asm("cvt.rn.f16x2.f32 %0, %1, %2;" : "=r"(r) : "f"(hi), "f"(lo)); return r;
}
__device__ __forceinline__ float lo_f(uint32_t x){ return __low2float(*(__half2*)&x); }
__device__ __forceinline__ float hi_f(uint32_t x){ return __high2float(*(__half2*)&x); }
__device__ __forceinline__ float ex2f(float x){ float r; asm("ex2.approx.f32 %0, %1;":"=f"(r):"f"(x)); return r; }
__device__ __forceinline__ void mma16816(float* c, const uint32_t* a, uint2 b){
    asm volatile("mma.sync.aligned.m16n8k16.row.col.f32.f16.f16.f32 "
      "{%0,%1,%2,%3}, {%4,%5,%6,%7}, {%8,%9}, {%0,%1,%2,%3};"
      : "+f"(c[0]),"+f"(c[1]),"+f"(c[2]),"+f"(c[3])
      : "r"(a[0]),"r"(a[1]),"r"(a[2]),"r"(a[3]),"r"(b.x),"r"(b.y));
}
__device__ __forceinline__ uint32_t smem_u32(const void* p){
    uint32_t a; asm("{ .reg .u64 t; cvta.to.shared.u64 t, %1; cvt.u32.u64 %0, t; }":"=r"(a):"l"(p)); return a;
}
__device__ __forceinline__ void cpa16(uint32_t dst, const void* src){
    asm volatile("cp.async.cg.shared.global [%0], [%1], 16;"::"r"(dst),"l"(src));
}
__device__ __forceinline__ void cpa_commit(){ asm volatile("cp.async.commit_group;":::"memory"); }
template<int N> __device__ __forceinline__ void cpa_wait(){ asm volatile("cp.async.wait_group %0;"::"n"(N):"memory"); }

#define L2E 1.4426950408889634f

// =================================================================
// Launch 0: prep (packW x4 [0,256), packW2 [256,264), mask [264])
// =================================================================
__global__ __launch_bounds__(256) void prep_kernel(
    const float* __restrict__ Wq, const float* __restrict__ Wk, const float* __restrict__ Wv,
    const float* __restrict__ Wp, const float* __restrict__ W2x, const float* __restrict__ W2y,
    const unsigned char* __restrict__ mask,
    uint2* __restrict__ wqf, uint2* __restrict__ wkf, uint2* __restrict__ wvf,
    uint2* __restrict__ wpfh, uint2* __restrict__ wpfl,
    uint2* __restrict__ w2fh, uint2* __restrict__ w2fl, unsigned* __restrict__ mb)
{
    const int blk=blockIdx.x, tid=threadIdx.x;
    if (blk < 256){
        const float* W; uint2 *fh, *fl=nullptr;
        int base;
        if (blk < 64){ W=Wq; fh=wqf; base=0; }
        else if (blk < 128){ W=Wk; fh=wkf; base=64; }
        else if (blk < 192){ W=Wv; fh=wvf; base=128; }
        else { W=Wp; fh=wpfh; fl=wpfl; base=192; }
        int idx=(blk-base)*256+tid;
        int lane=idx&31, ks=(idx>>5)&15, n8=idx>>9;
        int k0=ks*16+(lane&3)*2, n=n8*8+(lane>>2);
        float w00=W[k0*256+n], w01=W[(k0+1)*256+n], w08=W[(k0+8)*256+n], w09=W[(k0+9)*256+n];
        uint2 hi=make_uint2(pack_h2(w00,w01), pack_h2(w08,w09));
        fh[idx]=hi;
        if (fl) fl[idx]=make_uint2(pack_h2(w00-lo_f(hi.x), w01-hi_f(hi.x)),
                                   pack_h2(w08-lo_f(hi.y), w09-hi_f(hi.y)));
        return;
    }
    if (blk < 264){
        int idx=(blk-256)*256+tid;
        int axis=idx>>10, r=idx&1023, lane=r&31, ks=r>>5;
        int j0=ks*16+(lane&3)*2, h=lane>>2;
        const float* W2=axis?W2y:W2x;
        float w00=W2[j0*8+h], w01=W2[(j0+1)*8+h], w08=W2[(j0+8)*8+h], w09=W2[(j0+9)*8+h];
        uint2 hi=make_uint2(pack_h2(w00,w01), pack_h2(w08,w09));
        w2fh[idx]=hi;
        w2fl[idx]=make_uint2(pack_h2(w00-lo_f(hi.x), w01-hi_f(hi.x)),
                             pack_h2(w08-lo_f(hi.y), w09-hi_f(hi.y)));
        return;
    }
    if (tid < BB*128){
        const unsigned char* p=mask+tid*32;
        unsigned v=0;
        #pragma unroll
        for (int i=0;i<32;i++) v |= (p[i]?1u:0u)<<i;
        mb[tid]=v;
    }
}

// =================================================================
// Launch 1: fused Q/K/V projection GEMM, grid (4, 128, 3).
// z=0: Q -> fp32*(scale*log2e); z=1: K -> Kf fragments DIRECT;
// z=2: V -> Vf fragments via smem transpose.
// =================================================================
__global__ __launch_bounds__(256) void gemm_all_kernel(
    const float* __restrict__ qa, const float* __restrict__ ka, const float* __restrict__ va,
    const uint2* __restrict__ wq, const uint2* __restrict__ wk, const uint2* __restrict__ wv,
    const float* __restrict__ bq, const float* __restrict__ bk, const float* __restrict__ bv,
    float* __restrict__ qout, uint2* __restrict__ Kf, uint2* __restrict__ Vf, float qscale)
{
    __shared__ __half vs[64][72];
    const int z=blockIdx.z;
    const float* A; const uint2* Wf; const float* bias; int M;
    if (z==0){ A=qa; Wf=wq; bias=bq; M=BB*NQ; }
    else if (z==1){ A=ka; Wf=wk; bias=bk; M=BB*NN; }
    else { A=va; Wf=wv; bias=bv; M=BB*NN; }
    const int bm=blockIdx.y*64;
    if (bm >= M) return;
    const int tid=threadIdx.x, wid=tid>>5, lane=tid&31;
    const int g=lane>>2, tg=lane&3;
    const int wrow=wid>>1, wcol=wid&1;
    const int bn=blockIdx.x*64;
    const int r0=bm+wrow*16+g, r1=r0+8;
    const int r0c=r0<M?r0:M-1, r1c=r1<M?r1:M-1;
    const uint2* wf=Wf+((bn>>3)+wcol*4)*512+lane;
    float c[4][4]={};
    #pragma unroll
    for (int ks=0;ks<16;ks++){
        const int k0=ks*16+tg*2;
        float2 v0=*(const float2*)&A[r0c*256+k0];
        float2 v1=*(const float2*)&A[r1c*256+k0];
        float2 v2=*(const float2*)&A[r0c*256+k0+8];
        float2 v3=*(const float2*)&A[r1c*256+k0+8];
        uint32_t a[4];
        a[0]=pack_h2(v0.x,v0.y);
        a[1]=pack_h2(v1.x,v1.y);
        a[2]=pack_h2(v2.x,v2.y);
        a[3]=pack_h2(v3.x,v3.y);
        #pragma unroll
        for (int nt=0;nt<4;nt++) mma16816(c[nt], a, wf[nt*512+ks*32]);
    }
    const int cn=bn+wcol*32;
    if (z==0){
        #pragma unroll
        for (int nt=0;nt<4;nt++){
            int col=cn+nt*8+tg*2;
            float b0=bias[col], b1=bias[col+1];
            if (r0<M){ float2 o=make_float2((c[nt][0]+b0)*qscale,(c[nt][1]+b1)*qscale); *(float2*)&qout[r0*256+col]=o; }
            if (r1<M){ float2 o=make_float2((c[nt][2]+b0)*qscale,(c[nt][3]+b1)*qscale); *(float2*)&qout[r1*256+col]=o; }
        }
    } else if (z==1){
        // direct Kf fragment write: rows always valid (M=8192)
        const int b=r0>>12;
        const int kt8a=(r0&4095)>>3;      // g<8 so same for quad; even
        const int h=(bn>>5)+wcol;
        const size_t base=(size_t)(b*8+h)*32768;
        #pragma unroll
        for (int ds=0;ds<2;ds++){
            const int nlo=2*ds, nhi=2*ds+1;
            int clo=cn+nlo*8+tg*2, chi=cn+nhi*8+tg*2;
            float blo0=bias[clo], blo1=bias[clo+1];
            float bhi0=bias[chi], bhi1=bias[chi+1];
            Kf[base + ((size_t)kt8a*2+ds)*32 + lane] = make_uint2(
                pack_h2(c[nlo][0]+blo0, c[nlo][1]+blo1),
                pack_h2(c[nhi][0]+bhi0, c[nhi][1]+bhi1));
            Kf[base + ((size_t)(kt8a+1)*2+ds)*32 + lane] = make_uint2(
                pack_h2(c[nlo][2]+blo0, c[nlo][3]+blo1),
                pack_h2(c[nhi][2]+bhi0, c[nhi][3]+bhi1));
        }
    } else {
        // V: stage fp16(c+bias) in smem, then transposed Vf fragment write
        const int rl0=r0&63, rl1=rl0+8;
        #pragma unroll
        for (int nt=0;nt<4;nt++){
            int col=cn+nt*8+tg*2;
            float b0=bias[col], b1=bias[col+1];
            int cl=col&63;
            *(__half2*)&vs[rl0][cl]=__floats2half2_rn(c[nt][0]+b0,c[nt][1]+b1);
            *(__half2*)&vs[rl1][cl]=__floats2half2_rn(c[nt][2]+b0,c[nt][3]+b1);
        }
        __syncthreads();
        const int b=bm>>12;
        const int hloc=tid>>7;            // 0..1
        const int kt16loc=(tid>>5)&3;     // 0..3
        const int lane2=tid&31;
        const int h=(bn>>5)+hloc;
        const int kt16=((bm&4095)>>4)+kt16loc;
        const int key0=kt16loc*16+(lane2&3)*2;
        const size_t vb=(size_t)(b*8+h)*32768 + (size_t)kt16*128;
        #pragma unroll
        for (int nt=0;nt<4;nt++){
            int d=hloc*32+nt*8+(lane2>>2);
            uint2 o;
            o.x=(uint32_t)__half_as_ushort(vs[key0][d])   | ((uint32_t)__half_as_ushort(vs[key0+1][d])<<16);
            o.y=(uint32_t)__half_as_ushort(vs[key0+8][d]) | ((uint32_t)__half_as_ushort(vs[key0+9][d])<<16);
            Vf[vb + nt*32 + lane2]=o;
        }
    }
}

// =================================================================
// Launch 2: RPE (alpha/beta trick + 3-term hi/lo HMMA). grid 1800.
// =================================================================
__global__ __launch_bounds__(256) void rpe_kernel(
    const float* __restrict__ ref,
    const float* __restrict__ W1x, const float* __restrict__ b1x,
    const float* __restrict__ W1y, const float* __restrict__ b1y,
    const uint2* __restrict__ w2fh, const uint2* __restrict__ w2fl,
    float* __restrict__ rx, float* __restrict__ ry)
{
    __shared__ float2 sAB[2][512];
    const int bq=blockIdx.x, b=bq/NQ, q=bq-b*NQ, tid=threadIdx.x;
    float4 box=*(const float4*)&ref[bq*4];
    float lox=box.x-box.z*0.5f, hix=box.x+box.z*0.5f;
    float loy=box.y-box.w*0.5f, hiy=box.y+box.w*0.5f;
    for (int idx=tid; idx<1024; idx+=256){
        int axis=idx>>9, j=idx&511;
        const float* W1=axis?W1y:W1x;
        float u=W1[j], v=W1[512+j];
        float bb=(axis?b1y:b1x)[j];
        float LO=axis?loy:lox, HI=axis?hiy:hix;
        sAB[axis][j]=make_float2(fmaf(LO,u,fmaf(HI,v,bb)), u+v);
    }
    __syncthreads();
    const int wid=tid>>5, lane=tid&31, g=lane>>2, tg=lane&3;
    const int axis=wid>>2, mt=wid&3;
    const float p0=((float)(mt*16+g)+0.5f)*16.f;
    const float p1=p0+128.f;
    const uint2* fh=w2fh+axis*1024+lane;
    const uint2* fl=w2fl+axis*1024+lane;
    const float2* AB=sAB[axis];
    float c[4]={0.f,0.f,0.f,0.f};
    #pragma unroll 4
    for (int ks=0;ks<32;ks++){
        int j0=ks*16+tg*2;
        float2 ab0=AB[j0], ab1=AB[j0+1], ab8=AB[j0+8], ab9=AB[j0+9];
        float h00=fmaxf(fmaf(-p0,ab0.y,ab0.x),0.f);
        float h01=fmaxf(fmaf(-p0,ab1.y,ab1.x),0.f);
        float h10=fmaxf(fmaf(-p1,ab0.y,ab0.x),0.f);
        float h11=fmaxf(fmaf(-p1,ab1.y,ab1.x),0.f);
        float h08=fmaxf(fmaf(-p0,ab8.y,ab8.x),0.f);
        float h09=fmaxf(fmaf(-p0,ab9.y,ab9.x),0.f);
        float h18=fmaxf(fmaf(-p1,ab8.y,ab8.x),0.f);
        float h19=fmaxf(fmaf(-p1,ab9.y,ab9.x),0.f);
        uint32_t ah[4], al[4];
        ah[0]=pack_h2(h00,h01); ah[1]=pack_h2(h10,h11);
        ah[2]=pack_h2(h08,h09); ah[3]=pack_h2(h18,h19);
        al[0]=pack_h2(h00-lo_f(ah[0]), h01-hi_f(ah[0]));
        al[1]=pack_h2(h10-lo_f(ah[1]), h11-hi_f(ah[1]));
        al[2]=pack_h2(h08-lo_f(ah[2]), h09-hi_f(ah[2]));
        al[3]=pack_h2(h18-lo_f(ah[3]), h19-hi_f(ah[3]));
        uint2 bh=fh[ks*32], bl=fl[ks*32];
        mma16816(c, ah, bh);
        mma16816(c, ah, bl);
        mma16816(c, al, bh);
    }
    float* outp=axis?ry:rx;
    const int h2=tg*2, pos0=mt*16+g;
    size_t base0=((size_t)(b*8+h2)*NQ+q)*64;
    size_t base1=((size_t)(b*8+h2+1)*NQ+q)*64;
    outp[base0+pos0]    =c[0]*L2E;
    outp[base1+pos0]    =c[1]*L2E;
    outp[base0+pos0+8]  =c[2]*L2E;
    outp[base1+pos0+8]  =c[3]*L2E;
}

// =================================================================
// Launch 3 (PROFILED): HMMA flash attention, 2-way key split,
// cp.async double-buffered smem staging.  grid (8, 16, 2)
// =================================================================
__global__ __launch_bounds__(256) void attn_hmma_kernel(
    const float* __restrict__ qp, const uint2* __restrict__ Kf, const uint2* __restrict__ Vf,
    const float* __restrict__ rxg, const float* __restrict__ ryg,
    const unsigned* __restrict__ mbits, float* __restrict__ aop, float* __restrict__ lp)
{
    __shared__ uint2 sbuf[2][2048];   // [buf][ kf 1024 | vf 1024 ] = 2 x 16KB
    const int tid=threadIdx.x, wid=tid>>5, lane=tid&31;
    const int g=lane>>2, tg=lane&3;
    const int bh=blockIdx.y, b=bh>>3, h=bh&7;
    const int z=blockIdx.z;
    const int q0=blockIdx.x*128 + wid*16;
    int qr[2]={q0+g, q0+g+8};
    int qc[2]={qr[0]<NQ?qr[0]:NQ-1, qr[1]<NQ?qr[1]:NQ-1};

    const uint2* KfB=Kf+(size_t)bh*32768;
    const uint2* VfB=Vf+(size_t)bh*32768;
    const uint32_t sb0=smem_u32(sbuf);

    // prologue prefetch: tile z*16 -> buf0
    {
        const char* ks_=(const char*)(KfB+(size_t)(z*16)*1024);
        const char* vs_=(const char*)(VfB+(size_t)(z*16)*1024);
        uint32_t d=sb0+tid*16;
        cpa16(d,        ks_+tid*16);
        cpa16(d+4096,   ks_+4096+tid*16);
        cpa16(d+8192,   vs_+tid*16);
        cpa16(d+12288,  vs_+4096+tid*16);
        cpa_commit();
    }

    uint32_t qf[2][4];
    #pragma unroll
    for (int ds=0;ds<2;ds++)
        #pragma unroll
        for (int r=0;r<2;r++){
            const float* p=qp+((size_t)b*NQ+qc[r])*CC+h*32+ds*16+tg*2;
            qf[ds][r]  =pack_h2(p[0],p[1]);
            qf[ds][r+2]=pack_h2(p[8],p[9]);
        }

    float rxv[2][16], shift[2];
    #pragma unroll
    for (int r=0;r<2;r++){
        const float* rp=rxg+((size_t)bh*NQ+qc[r])*64;
        float mx=-1e30f;
        #pragma unroll
        for (int j=0;j<8;j++){
            float2 v=*(const float2*)&rp[j*8+tg*2];
            rxv[r][j*2]=v.x; rxv[r][j*2+1]=v.y;
            mx=fmaxf(mx,fmaxf(v.x,v.y));
        }
        mx=fmaxf(mx,__shfl_xor_sync(0xffffffffu,mx,1));
        mx=fmaxf(mx,__shfl_xor_sync(0xffffffffu,mx,2));
        const float* yp=ryg+((size_t)bh*NQ+qc[r])*64;
        float my=-1e30f;
        #pragma unroll
        for (int j=0;j<16;j++) my=fmaxf(my,yp[tg+4*j]);
        my=fmaxf(my,__shfl_xor_sync(0xffffffffu,my,1));
        my=fmaxf(my,__shfl_xor_sync(0xffffffffu,my,2));
        shift[r]=mx+my;
    }

    const uint2 onesb = (lane<4)? make_uint2(0x3C003C00u,0x3C003C00u) : make_uint2(0u,0u);
    float Oacc[4][4];
    #pragma unroll
    for (int i=0;i<4;i++)
        #pragma unroll
        for (int j=0;j<4;j++) Oacc[i][j]=0.f;
    float ls[4]={0.f,0.f,0.f,0.f};

    for (int tt=0; tt<16; tt++){
        const int t=z*16+tt;
        __syncthreads();
        if (tt<15){
            const char* ks_=(const char*)(KfB+(size_t)(t+1)*1024);
            const char* vs_=(const char*)(VfB+(size_t)(t+1)*1024);
            uint32_t d=sb0+((tt+1)&1)*16384+tid*16;
            cpa16(d,        ks_+tid*16);
            cpa16(d+4096,   ks_+4096+tid*16);
            cpa16(d+8192,   vs_+tid*16);
            cpa16(d+12288,  vs_+4096+tid*16);
            cpa_commit();
            cpa_wait<1>();
        } else {
            cpa_wait<0>();
        }
        __syncthreads();

        const uint2* kbuf=sbuf[tt&1];
        const uint2* vbuf=kbuf+1024;

        float cp0[2][2], cp1[2][2];
        #pragma unroll
        for (int r=0;r<2;r++){
            const float* yp=ryg+((size_t)bh*NQ+qc[r])*64+2*t;
            cp0[r][0]=yp[0]-shift[r];
            cp0[r][1]=yp[1]-shift[r];
            cp1[r][0]=cp0[r][0]-144.26950408889634f;
            cp1[r][1]=cp0[r][1]-144.26950408889634f;
        }
        unsigned mbw[4];
        #pragma unroll
        for (int j=0;j<4;j++) mbw[j]=mbits[b*128+t*4+j];

        #pragma unroll
        for (int ks=0;ks<8;ks++){
            float sc[2][4];
            #pragma unroll
            for (int j=0;j<2;j++)
                #pragma unroll
                for (int i=0;i<4;i++) sc[j][i]=0.f;
            #pragma unroll
            for (int j=0;j<2;j++){
                const uint2* kf=kbuf+(2*ks+j)*64+lane;
                mma16816(sc[j], qf[0], kf[0]);
                mma16816(sc[j], qf[1], kf[32]);
            }
            float pv[2][4];
            const int yp=ks>>2;
            #pragma unroll
            for (int j=0;j<2;j++){
                const int nt=2*ks+j;
                #pragma unroll
                for (int i=0;i<4;i++){
                    const int row=i>>1, e=i&1;
                    bool mbit=(mbw[nt>>2]>>((nt&3)*8+tg*2+e))&1u;
                    float s=sc[j][i]+rxv[row][(nt&7)*2+e];
                    float cp=mbit?cp1[row][yp]:cp0[row][yp];
                    pv[j][i]=ex2f(s+cp);
                }
            }
            uint32_t pa[4];
            pa[0]=pack_h2(pv[0][0],pv[0][1]);
            pa[1]=pack_h2(pv[0][2],pv[0][3]);
            pa[2]=pack_h2(pv[1][0],pv[1][1]);
            pa[3]=pack_h2(pv[1][2],pv[1][3]);
            mma16816(ls, pa, onesb);
            const uint2* vf=vbuf+ks*128+lane;
            #pragma unroll
            for (int nv=0;nv<4;nv++)
                mma16816(Oacc[nv], pa, vf[nv*32]);
        }
    }

    if (tg==0){
        if (qr[0]<NQ) lp[(size_t)z*BB*HH*NQ + (size_t)bh*NQ + qr[0]] = ls[0];
        if (qr[1]<NQ) lp[(size_t)z*BB*HH*NQ + (size_t)bh*NQ + qr[1]] = ls[2];
    }
    #pragma unroll
    for (int r=0;r<2;r++){
        if (qr[r]<NQ){
            float* dst=aop + (size_t)z*BB*NQ*CC + ((size_t)b*NQ+qr[r])*CC + h*32;
            #pragma unroll
            for (int nv=0;nv<4;nv++){
                float2 o=make_float2(Oacc[nv][2*r], Oacc[nv][2*r+1]);
                *(float2*)&dst[nv*8+tg*2]=o;
            }
        }
    }
}

// =================================================================
// Launch 4: combine ksplit partials + normalize + fp16 hi/lo split
// =================================================================
__global__ __launch_bounds__(256) void pack_ao_kernel(
    const float* __restrict__ aop, const float* __restrict__ lp,
    __half* __restrict__ oh, __half* __restrict__ ol)
{
    int i=blockIdx.x*256+threadIdx.x;
    if (i < BB*NQ*CC){
        int bq=i>>8, q=bq%NQ, b=bq/NQ, h=(i>>5)&7;
        size_t li=(size_t)(b*8+h)*NQ+q;
        float l=0.f, v=0.f;
        #pragma unroll
        for (int zz=0;zz<KSPLIT;zz++){
            l+=lp[(size_t)zz*BB*HH*NQ+li];
            v+=aop[(size_t)zz*BB*NQ*CC+i];
        }
        v/=l;
        __half hh=__float2half_rn(v);
        oh[i]=hh; ol[i]=__float2half_rn(v-__half2float(hh));
    }
}

// =================================================================
// Launch 5: output projection, 3-term hi/lo HMMA
// =================================================================
__global__ __launch_bounds__(256) void gemm_h3_kernel(
    const __half* __restrict__ Ah, const __half* __restrict__ Al,
    const uint2* __restrict__ Wfh, const uint2* __restrict__ Wfl,
    const float* __restrict__ bias, float* __restrict__ out, int M)
{
    const int tid=threadIdx.x, wid=tid>>5, lane=tid&31;
    const int g=lane>>2, tg=lane&3;
    const int wrow=wid>>1, wcol=wid&1;
    const int bm=blockIdx.y*64, bn=blockIdx.x*64;
    const int r0=bm+wrow*16+g, r1=r0+8;
    const int r0c=r0<M?r0:M-1, r1c=r1<M?r1:M-1;
    const int fbase=((bn>>3)+wcol*4)*512+lane;
    float c[4][4]={};
    #pragma unroll
    for (int ks=0;ks<16;ks++){
        const int k0=ks*16+tg*2;
        uint32_t ah[4], al[4];
        ah[0]=*(const uint32_t*)&Ah[r0c*256+k0];
        ah[1]=*(const uint32_t*)&Ah[r1c*256+k0];
        ah[2]=*(const uint32_t*)&Ah[r0c*256+k0+8];
        ah[3]=*(const uint32_t*)&Ah[r1c*256+k0+8];
        al[0]=*(const uint32_t*)&Al[r0c*256+k0];
        al[1]=*(const uint32_t*)&Al[r1c*256+k0];
        al[2]=*(const uint32_t*)&Al[r0c*256+k0+8];
        al[3]=*(const uint32_t*)&Al[r1c*256+k0+8];
        #pragma unroll
        for (int nt=0;nt<4;nt++){
            uint2 bh=Wfh[fbase+nt*512+ks*32];
            uint2 bl=Wfl[fbase+nt*512+ks*32];
            mma16816(c[nt], ah, bh);
            mma16816(c[nt], ah, bl);
            mma16816(c[nt], al, bh);
        }
    }
    const int cn=bn+wcol*32;
    #pragma unroll
    for (int nt=0;nt<4;nt++){
        int col=cn+nt*8+tg*2;
        float b0=bias[col], b1=bias[col+1];
        if (r0<M){ float2 o=make_float2(c[nt][0]+b0,c[nt][1]+b1); *(float2*)&out[r0*256+col]=o; }
        if (r1<M){ float2 o=make_float2(c[nt][2]+b0,c[nt][3]+b1); *(float2*)&out[r1*256+col]=o; }
    }
}

// ---------------- launch ----------------
extern "C" void kernel_launch(void* const* d_in, const int* in_sizes, int n_in,
                              void* d_out, int out_size)
{
    const float* query=(const float*)d_in[1];
    const float* ref  =(const float*)d_in[2];
    const float* kin  =(const float*)d_in[3];
    const float* vin  =(const float*)d_in[4];
    const unsigned char* mask=(const unsigned char*)d_in[6];
    const float* W1x=(const float*)d_in[7];
    const float* b1x=(const float*)d_in[8];
    const float* W2x=(const float*)d_in[9];
    const float* W1y=(const float*)d_in[10];
    const float* b1y=(const float*)d_in[11];
    const float* W2y=(const float*)d_in[12];
    const float* Wq =(const float*)d_in[13];
    const float* bq =(const float*)d_in[14];
    const float* Wk =(const float*)d_in[15];
    const float* bk =(const float*)d_in[16];
    const float* Wv =(const float*)d_in[17];
    const float* bv =(const float*)d_in[18];
    const float* Wp =(const float*)d_in[19];
    const float* bp =(const float*)d_in[20];
    float* out=(float*)d_out;

    void *pq,*pwq,*pwk,*pwv,*pwph,*pwpl,*pw2h,*pw2l;
    void *pkf,*pvf,*pmb,*prx,*pry,*paop,*plp,*paoh,*paol;
    cudaGetSymbolAddress(&pq,  g_q);
    cudaGetSymbolAddress(&pwq, g_wqf);
    cudaGetSymbolAddress(&pwk, g_wkf);
    cudaGetSymbolAddress(&pwv, g_wvf);
    cudaGetSymbolAddress(&pwph,g_wpfh);
    cudaGetSymbolAddress(&pwpl,g_wpfl);
    cudaGetSymbolAddress(&pw2h,g_w2fh);
    cudaGetSymbolAddress(&pw2l,g_w2fl);
    cudaGetSymbolAddress(&pkf, g_kf);
    cudaGetSymbolAddress(&pvf, g_vf);
    cudaGetSymbolAddress(&pmb, g_mb);
    cudaGetSymbolAddress(&prx, g_rx);
    cudaGetSymbolAddress(&pry, g_ry);
    cudaGetSymbolAddress(&paop,g_aop);
    cudaGetSymbolAddress(&plp, g_lp);
    cudaGetSymbolAddress(&paoh,g_aoh);
    cudaGetSymbolAddress(&paol,g_aol);

    const float qscale=(float)(0.17677669529663687 * 1.4426950408889634);
    const int MQ=BB*NQ;

    prep_kernel<<<265,256>>>(Wq,Wk,Wv,Wp,W2x,W2y,mask,
        (uint2*)pwq,(uint2*)pwk,(uint2*)pwv,(uint2*)pwph,(uint2*)pwpl,
        (uint2*)pw2h,(uint2*)pw2l,(unsigned*)pmb);
    gemm_all_kernel<<<dim3(4,128,3),256>>>(query,kin,vin,
        (const uint2*)pwq,(const uint2*)pwk,(const uint2*)pwv,bq,bk,bv,
        (float*)pq,(uint2*)pkf,(uint2*)pvf,qscale);
    rpe_kernel<<<MQ,256>>>(ref,W1x,b1x,W1y,b1y,
        (const uint2*)pw2h,(const uint2*)pw2l,(float*)prx,(float*)pry);
    attn_hmma_kernel<<<dim3(8,BB*HH,KSPLIT),256>>>(
        (const float*)pq,(const uint2*)pkf,(const uint2*)pvf,
        (const float*)prx,(const float*)pry,(const unsigned*)pmb,(float*)paop,(float*)plp);
    pack_ao_kernel<<<(MQ*CC+255)/256,256>>>((const float*)paop,(const float*)plp,(__half*)paoh,(__half*)paol);
    gemm_h3_kernel<<<dim3(4,(MQ+63)/64),256>>>((const __half*)paoh,(const __half*)paol,
        (const uint2*)pwph,(const uint2*)pwpl,bp,out,MQ);
}